// round 1
// baseline (speedup 1.0000x reference)
#include <cuda_runtime.h>
#include <math.h>

#define NN 50000
#define NE 800000
#define ETOT (NE + NN)
#define NEG 0.2f
#define EPSV 1e-16f

// ---------------- scratch (device globals; no allocation allowed) ----------
__device__ __align__(16) float g_mid[NN * 64];
__device__ __align__(16) float g_h0 [NN * 64];
__device__ __align__(16) float g_h1 [NN * 256];
__device__ __align__(16) float g_o1 [NN * 256];
__device__ __align__(16) float g_h2 [NN * 64];
__device__ __align__(16) float g_o2 [NN * 64];
__device__ __align__(16) float g_as [NN * 4];
__device__ __align__(16) float g_ad [NN * 4];
__device__ int g_deg[NN];
__device__ int g_off[NN + 1];
__device__ int g_cur[NN];
__device__ int g_srcs[ETOT];

// ---------------- CSR build ----------------
__global__ void k_zero_deg() {
    int i = blockIdx.x * blockDim.x + threadIdx.x;
    if (i < NN) g_deg[i] = 0;
}

__global__ void k_count(const int* __restrict__ ei) {
    int i = blockIdx.x * blockDim.x + threadIdx.x;
    if (i >= ETOT) return;
    int d = (i < NE) ? ei[NE + i] : (i - NE);
    atomicAdd(&g_deg[d], 1);
}

__global__ void k_scan() {
    __shared__ int sh[1024];
    int t = threadIdx.x;
    const int CH = (NN + 1023) / 1024;  // 49
    int b = t * CH;
    int e = b + CH; if (e > NN) e = NN;
    int s = 0;
    for (int i = b; i < e; i++) s += g_deg[i];
    sh[t] = s;
    __syncthreads();
    for (int o = 1; o < 1024; o <<= 1) {
        int v = 0;
        if (t >= o) v = sh[t - o];
        __syncthreads();
        sh[t] += v;
        __syncthreads();
    }
    int run = (t == 0) ? 0 : sh[t - 1];
    for (int i = b; i < e; i++) {
        g_off[i] = run;
        g_cur[i] = run;
        run += g_deg[i];
    }
    if (t == 1023) g_off[NN] = sh[1023];
}

__global__ void k_scatter(const int* __restrict__ ei) {
    int i = blockIdx.x * blockDim.x + threadIdx.x;
    if (i >= ETOT) return;
    int s, d;
    if (i < NE) { s = ei[i]; d = ei[NE + i]; }
    else        { s = i - NE; d = i - NE; }
    int p = atomicAdd(&g_cur[d], 1);
    g_srcs[p] = s;
}

// ---------------- encoder first layer (K=7) ----------------
__global__ void k_enc1(const float* __restrict__ x, const float* __restrict__ w1,
                       const float* __restrict__ b1) {
    int idx = blockIdx.x * blockDim.x + threadIdx.x;
    if (idx >= NN * 64) return;
    int n = idx >> 6, c = idx & 63;
    float s = b1[c];
#pragma unroll
    for (int k = 0; k < 7; k++) s += x[n * 7 + k] * w1[k * 64 + c];
    g_mid[idx] = fmaxf(s, 0.f);
}

// ---------------- generic tiled GEMM: C[M,Nc] = A[M,K] @ B[K,Nc] (+bias, act)
// K % 16 == 0, Nc % 64 == 0. act: 0 = none, 1 = relu.
__global__ void k_gemm(const float* __restrict__ A, const float* __restrict__ B,
                       const float* __restrict__ bias, float* __restrict__ C,
                       int M, int K, int Nc, int act) {
    __shared__ float As[16][64];
    __shared__ float Bs[16][64];
    int row0 = blockIdx.y * 64;
    int col0 = blockIdx.x * 64;
    int tid = threadIdx.x;
    int trow = (tid >> 4) << 2;
    int tcol = (tid & 15) << 2;
    float acc[4][4];
#pragma unroll
    for (int i = 0; i < 4; i++)
#pragma unroll
        for (int j = 0; j < 4; j++) acc[i][j] = 0.f;

    for (int k0 = 0; k0 < K; k0 += 16) {
#pragma unroll
        for (int j = 0; j < 4; j++) {
            int e = tid + 256 * j;
            int r = e >> 4, kk = e & 15;
            int row = row0 + r;
            As[kk][r] = (row < M) ? A[(size_t)row * K + k0 + kk] : 0.f;
            int kk2 = e >> 6, c = e & 63;
            Bs[kk2][c] = B[(size_t)(k0 + kk2) * Nc + col0 + c];
        }
        __syncthreads();
#pragma unroll
        for (int kk = 0; kk < 16; kk++) {
            float a0 = As[kk][trow], a1 = As[kk][trow + 1],
                  a2 = As[kk][trow + 2], a3 = As[kk][trow + 3];
            float b0 = Bs[kk][tcol], b1 = Bs[kk][tcol + 1],
                  b2 = Bs[kk][tcol + 2], b3 = Bs[kk][tcol + 3];
            acc[0][0] += a0 * b0; acc[0][1] += a0 * b1; acc[0][2] += a0 * b2; acc[0][3] += a0 * b3;
            acc[1][0] += a1 * b0; acc[1][1] += a1 * b1; acc[1][2] += a1 * b2; acc[1][3] += a1 * b3;
            acc[2][0] += a2 * b0; acc[2][1] += a2 * b1; acc[2][2] += a2 * b2; acc[2][3] += a2 * b3;
            acc[3][0] += a3 * b0; acc[3][1] += a3 * b1; acc[3][2] += a3 * b2; acc[3][3] += a3 * b3;
        }
        __syncthreads();
    }
#pragma unroll
    for (int i = 0; i < 4; i++) {
        int row = row0 + trow + i;
        if (row >= M) continue;
#pragma unroll
        for (int j = 0; j < 4; j++) {
            int col = col0 + tcol + j;
            float v = acc[i][j] + (bias ? bias[col] : 0.f);
            if (act == 1) v = fmaxf(v, 0.f);
            C[(size_t)row * Nc + col] = v;
        }
    }
}

// ---------------- per-node attention coefficients ----------------
template <int C>
__global__ void k_alpha(const float* __restrict__ hfeat,
                        const float* __restrict__ a_s, const float* __restrict__ a_d) {
    int warp = (blockIdx.x * blockDim.x + threadIdx.x) >> 5;
    int lane = threadIdx.x & 31;
    if (warp >= NN) return;
    const float* hrow = hfeat + (size_t)warp * 4 * C;
#pragma unroll
    for (int h = 0; h < 4; h++) {
        float ps = 0.f, pd = 0.f;
        for (int c = lane; c < C; c += 32) {
            float v = hrow[h * C + c];
            ps += v * a_s[h * C + c];
            pd += v * a_d[h * C + c];
        }
#pragma unroll
        for (int o = 16; o; o >>= 1) {
            ps += __shfl_xor_sync(0xffffffffu, ps, o);
            pd += __shfl_xor_sync(0xffffffffu, pd, o);
        }
        if (lane == 0) {
            g_as[warp * 4 + h] = ps;
            g_ad[warp * 4 + h] = pd;
        }
    }
}

__device__ __forceinline__ float lrelu(float e) { return e > 0.f ? e : NEG * e; }

// ---------------- fused GAT aggregate (softmax + weighted sum + bias + act)
// One warp per destination node. ACT: 0 = none, 1 = elu.
template <int C, int ACT>
__global__ void k_aggregate(const float* __restrict__ hfeat,
                            const float* __restrict__ bias,
                            float* __restrict__ out) {
    int warp = (blockIdx.x * blockDim.x + threadIdx.x) >> 5;
    int lane = threadIdx.x & 31;
    if (warp >= NN) return;
    int d = warp;
    int r0 = g_off[d];
    int deg = g_off[d + 1] - r0;
    float4 ad = ((const float4*)g_ad)[d];

    // pass 1: per-head max
    float m0 = -1e30f, m1 = -1e30f, m2 = -1e30f, m3 = -1e30f;
    for (int i = lane; i < deg; i += 32) {
        int s = g_srcs[r0 + i];
        float4 a = ((const float4*)g_as)[s];
        m0 = fmaxf(m0, lrelu(a.x + ad.x));
        m1 = fmaxf(m1, lrelu(a.y + ad.y));
        m2 = fmaxf(m2, lrelu(a.z + ad.z));
        m3 = fmaxf(m3, lrelu(a.w + ad.w));
    }
#pragma unroll
    for (int o = 16; o; o >>= 1) {
        m0 = fmaxf(m0, __shfl_xor_sync(0xffffffffu, m0, o));
        m1 = fmaxf(m1, __shfl_xor_sync(0xffffffffu, m1, o));
        m2 = fmaxf(m2, __shfl_xor_sync(0xffffffffu, m2, o));
        m3 = fmaxf(m3, __shfl_xor_sync(0xffffffffu, m3, o));
    }

    float s0 = 0.f, s1 = 0.f, s2 = 0.f, s3 = 0.f;

    if (C == 64) {
        float4 acc0 = {0.f, 0.f, 0.f, 0.f};
        float4 acc1 = {0.f, 0.f, 0.f, 0.f};
        bool lo = (lane < 16);
        for (int i = 0; i < deg; i++) {
            int s = g_srcs[r0 + i];
            float4 a = ((const float4*)g_as)[s];
            float w0 = __expf(lrelu(a.x + ad.x) - m0); s0 += w0;
            float w1 = __expf(lrelu(a.y + ad.y) - m1); s1 += w1;
            float w2 = __expf(lrelu(a.z + ad.z) - m2); s2 += w2;
            float w3 = __expf(lrelu(a.w + ad.w) - m3); s3 += w3;
            float wa = lo ? w0 : w1;
            float wb = lo ? w2 : w3;
            const float4* hp = (const float4*)(hfeat + (size_t)s * 256);
            float4 v = hp[lane];
            acc0.x += v.x * wa; acc0.y += v.y * wa; acc0.z += v.z * wa; acc0.w += v.w * wa;
            float4 u = hp[32 + lane];
            acc1.x += u.x * wb; acc1.y += u.y * wb; acc1.z += u.z * wb; acc1.w += u.w * wb;
        }
        float i0 = 1.f / (s0 + EPSV), i1 = 1.f / (s1 + EPSV);
        float i2 = 1.f / (s2 + EPSV), i3 = 1.f / (s3 + EPSV);
        float ia = lo ? i0 : i1;
        float ib = lo ? i2 : i3;
        float4 bA = ((const float4*)bias)[lane];
        float4 bB = ((const float4*)bias)[32 + lane];
        float4 rA, rB;
        rA.x = acc0.x * ia + bA.x; rA.y = acc0.y * ia + bA.y;
        rA.z = acc0.z * ia + bA.z; rA.w = acc0.w * ia + bA.w;
        rB.x = acc1.x * ib + bB.x; rB.y = acc1.y * ib + bB.y;
        rB.z = acc1.z * ib + bB.z; rB.w = acc1.w * ib + bB.w;
        if (ACT == 1) {
            rA.x = rA.x > 0.f ? rA.x : expm1f(rA.x);
            rA.y = rA.y > 0.f ? rA.y : expm1f(rA.y);
            rA.z = rA.z > 0.f ? rA.z : expm1f(rA.z);
            rA.w = rA.w > 0.f ? rA.w : expm1f(rA.w);
            rB.x = rB.x > 0.f ? rB.x : expm1f(rB.x);
            rB.y = rB.y > 0.f ? rB.y : expm1f(rB.y);
            rB.z = rB.z > 0.f ? rB.z : expm1f(rB.z);
            rB.w = rB.w > 0.f ? rB.w : expm1f(rB.w);
        }
        ((float4*)(out + (size_t)d * 256))[lane] = rA;
        ((float4*)(out + (size_t)d * 256))[32 + lane] = rB;
    } else {  // C == 16, HC = 64
        float2 acc = {0.f, 0.f};
        int head = lane >> 3;
        for (int i = 0; i < deg; i++) {
            int s = g_srcs[r0 + i];
            float4 a = ((const float4*)g_as)[s];
            float w0 = __expf(lrelu(a.x + ad.x) - m0); s0 += w0;
            float w1 = __expf(lrelu(a.y + ad.y) - m1); s1 += w1;
            float w2 = __expf(lrelu(a.z + ad.z) - m2); s2 += w2;
            float w3 = __expf(lrelu(a.w + ad.w) - m3); s3 += w3;
            float wm = head == 0 ? w0 : head == 1 ? w1 : head == 2 ? w2 : w3;
            float2 v = ((const float2*)(hfeat + (size_t)s * 64))[lane];
            acc.x += v.x * wm;
            acc.y += v.y * wm;
        }
        float im = head == 0 ? 1.f / (s0 + EPSV) : head == 1 ? 1.f / (s1 + EPSV)
                 : head == 2 ? 1.f / (s2 + EPSV) : 1.f / (s3 + EPSV);
        float2 bv = ((const float2*)bias)[lane];
        float2 r;
        r.x = acc.x * im + bv.x;
        r.y = acc.y * im + bv.y;
        ((float2*)(out + (size_t)d * 64))[lane] = r;
    }
}

// ---------------- decoder final layer [N,64] @ [64,4] ----------------
__global__ void k_dec2(const float* __restrict__ w2, const float* __restrict__ b2,
                       float* __restrict__ out) {
    int warp = (blockIdx.x * blockDim.x + threadIdx.x) >> 5;
    int lane = threadIdx.x & 31;
    if (warp >= NN) return;
    const float* mid = g_mid + (size_t)warp * 64;
    float4 acc = {0.f, 0.f, 0.f, 0.f};
#pragma unroll
    for (int k = lane; k < 64; k += 32) {
        float m = mid[k];
        float4 wv = ((const float4*)w2)[k];
        acc.x += m * wv.x; acc.y += m * wv.y;
        acc.z += m * wv.z; acc.w += m * wv.w;
    }
#pragma unroll
    for (int o = 16; o; o >>= 1) {
        acc.x += __shfl_xor_sync(0xffffffffu, acc.x, o);
        acc.y += __shfl_xor_sync(0xffffffffu, acc.y, o);
        acc.z += __shfl_xor_sync(0xffffffffu, acc.z, o);
        acc.w += __shfl_xor_sync(0xffffffffu, acc.w, o);
    }
    if (lane == 0) {
        out[warp * 4 + 0] = acc.x + b2[0];
        out[warp * 4 + 1] = acc.y + b2[1];
        out[warp * 4 + 2] = acc.z + b2[2];
        out[warp * 4 + 3] = acc.w + b2[3];
    }
}

// ---------------- launch ----------------
extern "C" void kernel_launch(void* const* d_in, const int* in_sizes, int n_in,
                              void* d_out, int out_size) {
    const float* x      = (const float*)d_in[0];
    const int*   ei     = (const int*)  d_in[1];
    const float* enc_w1 = (const float*)d_in[2];
    const float* enc_b1 = (const float*)d_in[3];
    const float* enc_w2 = (const float*)d_in[4];
    const float* enc_b2 = (const float*)d_in[5];
    const float* g1_w   = (const float*)d_in[6];
    const float* g1_as  = (const float*)d_in[7];
    const float* g1_ad  = (const float*)d_in[8];
    const float* g1_b   = (const float*)d_in[9];
    const float* g2_w   = (const float*)d_in[10];
    const float* g2_as  = (const float*)d_in[11];
    const float* g2_ad  = (const float*)d_in[12];
    const float* g2_b   = (const float*)d_in[13];
    const float* dec_w1 = (const float*)d_in[14];
    const float* dec_b1 = (const float*)d_in[15];
    const float* dec_w2 = (const float*)d_in[16];
    const float* dec_b2 = (const float*)d_in[17];
    float* out = (float*)d_out;

    float *mid, *h0, *h1, *o1, *h2, *o2;
    cudaGetSymbolAddress((void**)&mid, g_mid);
    cudaGetSymbolAddress((void**)&h0,  g_h0);
    cudaGetSymbolAddress((void**)&h1,  g_h1);
    cudaGetSymbolAddress((void**)&o1,  g_o1);
    cudaGetSymbolAddress((void**)&h2,  g_h2);
    cudaGetSymbolAddress((void**)&o2,  g_o2);

    const int WPB = 6250;  // 50000 warps / 8 warps-per-block

    // CSR build (reused by both GAT layers)
    k_zero_deg<<<(NN + 255) / 256, 256>>>();
    k_count<<<(ETOT + 255) / 256, 256>>>(ei);
    k_scan<<<1, 1024>>>();
    k_scatter<<<(ETOT + 255) / 256, 256>>>(ei);

    // encoder
    k_enc1<<<(NN * 64 + 255) / 256, 256>>>(x, enc_w1, enc_b1);
    k_gemm<<<dim3(1, (NN + 63) / 64), 256>>>(mid, enc_w2, enc_b2, h0, NN, 64, 64, 0);

    // GAT layer 1 (C=64, concat->256, ELU)
    k_gemm<<<dim3(4, (NN + 63) / 64), 256>>>(h0, g1_w, nullptr, h1, NN, 64, 256, 0);
    k_alpha<64><<<WPB, 256>>>(h1, g1_as, g1_ad);
    k_aggregate<64, 1><<<WPB, 256>>>(h1, g1_b, o1);

    // GAT layer 2 (C=16, concat->64, no act)
    k_gemm<<<dim3(1, (NN + 63) / 64), 256>>>(o1, g2_w, nullptr, h2, NN, 256, 64, 0);
    k_alpha<16><<<WPB, 256>>>(h2, g2_as, g2_ad);
    k_aggregate<16, 0><<<WPB, 256>>>(h2, g2_b, o2);

    // decoder
    k_gemm<<<dim3(1, (NN + 63) / 64), 256>>>(o2, dec_w1, dec_b1, mid, NN, 64, 64, 1);
    k_dec2<<<WPB, 256>>>(dec_w2, dec_b2, out);
}

// round 2
// speedup vs baseline: 1.4609x; 1.4609x over previous
#include <cuda_runtime.h>
#include <math.h>
#include <stdint.h>

#define NN 50000
#define NE 800000
#define ETOT (NE + NN)
#define NEG 0.2f
#define EPSV 1e-16f
#define NB1 49   // ceil(NN/1024)

// ---------------- scratch (device globals; no allocation allowed) ----------
__device__ __align__(16) float g_mid[NN * 64];
__device__ __align__(16) float g_h0 [NN * 64];
__device__ __align__(16) float g_h1 [NN * 256];
__device__ __align__(16) float g_o1 [NN * 256];
__device__ __align__(16) float g_h2 [NN * 64];
__device__ __align__(16) float g_o2 [NN * 64];
__device__ __align__(16) float g_as [NN * 4];
__device__ __align__(16) float g_ad [NN * 4];
__device__ int g_deg[NN];
__device__ int g_off[NN + 1];
__device__ int g_cur[NN];
__device__ int g_srcs[ETOT];
__device__ int g_bsum[NB1];
__device__ int g_boff[NB1];

// ---------------- CSR build ----------------
__global__ void k_zero_deg() {
    int i = blockIdx.x * blockDim.x + threadIdx.x;
    if (i < NN) g_deg[i] = 0;
}

__global__ void k_count(const int* __restrict__ ei) {
    int i = blockIdx.x * blockDim.x + threadIdx.x;
    if (i >= ETOT) return;
    int d = (i < NE) ? ei[NE + i] : (i - NE);
    atomicAdd(&g_deg[d], 1);
}

// phase 1: per-block sums (coalesced)
__global__ void k_bsum() {
    __shared__ int sh[1024];
    int t = threadIdx.x;
    int i = blockIdx.x * 1024 + t;
    sh[t] = (i < NN) ? g_deg[i] : 0;
    __syncthreads();
#pragma unroll
    for (int o = 512; o > 0; o >>= 1) {
        if (t < o) sh[t] += sh[t + o];
        __syncthreads();
    }
    if (t == 0) g_bsum[blockIdx.x] = sh[0];
}

// phase 2: scan the 49 block sums (exclusive)
__global__ void k_bscan() {
    __shared__ int sh[64];
    int t = threadIdx.x;
    int v = (t < NB1) ? g_bsum[t] : 0;
    sh[t] = v;
    __syncthreads();
#pragma unroll
    for (int o = 1; o < 64; o <<= 1) {
        int x = (t >= o) ? sh[t - o] : 0;
        __syncthreads();
        sh[t] += x;
        __syncthreads();
    }
    if (t < NB1) g_boff[t] = sh[t] - v;   // exclusive
}

// phase 3: per-block exclusive scan + block offset, write off/cur
__global__ void k_swrite() {
    __shared__ int sh[1024];
    int t = threadIdx.x;
    int i = blockIdx.x * 1024 + t;
    int v = (i < NN) ? g_deg[i] : 0;
    sh[t] = v;
    __syncthreads();
#pragma unroll
    for (int o = 1; o < 1024; o <<= 1) {
        int x = (t >= o) ? sh[t - o] : 0;
        __syncthreads();
        sh[t] += x;
        __syncthreads();
    }
    int incl = sh[t];
    int base = g_boff[blockIdx.x];
    if (i < NN) {
        int off = base + incl - v;
        g_off[i] = off;
        g_cur[i] = off;
        if (i == NN - 1) g_off[NN] = base + incl;
    }
}

__global__ void k_scatter(const int* __restrict__ ei) {
    int i = blockIdx.x * blockDim.x + threadIdx.x;
    if (i >= ETOT) return;
    int s, d;
    if (i < NE) { s = ei[i]; d = ei[NE + i]; }
    else        { s = i - NE; d = i - NE; }
    int p = atomicAdd(&g_cur[d], 1);
    g_srcs[p] = s;
}

// ---------------- encoder first layer (K=7) ----------------
__global__ void k_enc1(const float* __restrict__ x, const float* __restrict__ w1,
                       const float* __restrict__ b1) {
    int idx = blockIdx.x * blockDim.x + threadIdx.x;
    if (idx >= NN * 64) return;
    int n = idx >> 6, c = idx & 63;
    float s = b1[c];
#pragma unroll
    for (int k = 0; k < 7; k++) s += x[n * 7 + k] * w1[k * 64 + c];
    g_mid[idx] = fmaxf(s, 0.f);
}

// ---------------- tf32 tensor-core GEMM (3xTF32 split) ----------------
// C[M,Nc] = A[M,K] @ B[K,Nc] (+bias, act). BM=128, BN=64, BK=16.
// 256 threads = 8 warps as 4(M) x 2(N); warp tile 32x32.
__device__ __forceinline__ float tf32_rn(float x) {
    uint32_t u;
    asm("cvt.rna.tf32.f32 %0, %1;" : "=r"(u) : "f"(x));
    return __uint_as_float(u);
}

__device__ __forceinline__ void mma_tf32(float4& d, const uint32_t a[4], const uint32_t b[2]) {
    asm volatile(
        "mma.sync.aligned.m16n8k8.row.col.f32.tf32.tf32.f32 "
        "{%0,%1,%2,%3},{%4,%5,%6,%7},{%8,%9},{%0,%1,%2,%3};\n"
        : "+f"(d.x), "+f"(d.y), "+f"(d.z), "+f"(d.w)
        : "r"(a[0]), "r"(a[1]), "r"(a[2]), "r"(a[3]), "r"(b[0]), "r"(b[1]));
}

template <int ACT>  // 0 none, 1 relu
__global__ void k_mma_gemm(const float* __restrict__ A, const float* __restrict__ B,
                           const float* __restrict__ bias, float* __restrict__ C,
                           int M, int K, int Nc) {
    __shared__ float Ah[16][136], Al[16][136];  // [k][m] transposed, pad 8
    __shared__ float Bh[16][72],  Bl[16][72];   // [k][n], pad 8

    int tid  = threadIdx.x;
    int warp = tid >> 5, lane = tid & 31;
    int wm = warp >> 1, wn = warp & 1;
    int m0 = blockIdx.y * 128, n0 = blockIdx.x * 64;
    int grp = lane >> 2, tig = lane & 3;

    float4 acc[2][4];
#pragma unroll
    for (int i = 0; i < 2; i++)
#pragma unroll
        for (int j = 0; j < 4; j++) acc[i][j] = make_float4(0.f, 0.f, 0.f, 0.f);

    for (int k0 = 0; k0 < K; k0 += 16) {
        // A tile -> smem (transposed, hi/lo)
#pragma unroll
        for (int r = 0; r < 2; r++) {
            int idx = tid + 256 * r;          // 0..511 float4 slots
            int m = idx >> 2, kq = idx & 3;
            int row = m0 + m;
            float4 v = make_float4(0.f, 0.f, 0.f, 0.f);
            if (row < M) v = *(const float4*)(A + (size_t)row * K + k0 + 4 * kq);
            float h;
            h = tf32_rn(v.x); Ah[4*kq+0][m] = h; Al[4*kq+0][m] = tf32_rn(v.x - h);
            h = tf32_rn(v.y); Ah[4*kq+1][m] = h; Al[4*kq+1][m] = tf32_rn(v.y - h);
            h = tf32_rn(v.z); Ah[4*kq+2][m] = h; Al[4*kq+2][m] = tf32_rn(v.z - h);
            h = tf32_rn(v.w); Ah[4*kq+3][m] = h; Al[4*kq+3][m] = tf32_rn(v.w - h);
        }
        // B tile -> smem (hi/lo)
        {
            int kk = tid >> 4, nq = tid & 15;
            float4 v = *(const float4*)(B + (size_t)(k0 + kk) * Nc + n0 + 4 * nq);
            float4 hv, lv;
            hv.x = tf32_rn(v.x); lv.x = tf32_rn(v.x - hv.x);
            hv.y = tf32_rn(v.y); lv.y = tf32_rn(v.y - hv.y);
            hv.z = tf32_rn(v.z); lv.z = tf32_rn(v.z - hv.z);
            hv.w = tf32_rn(v.w); lv.w = tf32_rn(v.w - hv.w);
            *(float4*)&Bh[kk][4 * nq] = hv;
            *(float4*)&Bl[kk][4 * nq] = lv;
        }
        __syncthreads();

#pragma unroll
        for (int ks = 0; ks < 2; ks++) {
            int kb = ks * 8;
            uint32_t aH[2][4], aL[2][4];
#pragma unroll
            for (int mt = 0; mt < 2; mt++) {
                int mb = wm * 32 + mt * 16 + grp;
                aH[mt][0] = __float_as_uint(Ah[kb + tig    ][mb]);
                aH[mt][1] = __float_as_uint(Ah[kb + tig    ][mb + 8]);
                aH[mt][2] = __float_as_uint(Ah[kb + tig + 4][mb]);
                aH[mt][3] = __float_as_uint(Ah[kb + tig + 4][mb + 8]);
                aL[mt][0] = __float_as_uint(Al[kb + tig    ][mb]);
                aL[mt][1] = __float_as_uint(Al[kb + tig    ][mb + 8]);
                aL[mt][2] = __float_as_uint(Al[kb + tig + 4][mb]);
                aL[mt][3] = __float_as_uint(Al[kb + tig + 4][mb + 8]);
            }
#pragma unroll
            for (int nt = 0; nt < 4; nt++) {
                int nb = wn * 32 + nt * 8 + grp;
                uint32_t bH[2], bL[2];
                bH[0] = __float_as_uint(Bh[kb + tig    ][nb]);
                bH[1] = __float_as_uint(Bh[kb + tig + 4][nb]);
                bL[0] = __float_as_uint(Bl[kb + tig    ][nb]);
                bL[1] = __float_as_uint(Bl[kb + tig + 4][nb]);
#pragma unroll
                for (int mt = 0; mt < 2; mt++) {
                    mma_tf32(acc[mt][nt], aH[mt], bH);
                    mma_tf32(acc[mt][nt], aL[mt], bH);
                    mma_tf32(acc[mt][nt], aH[mt], bL);
                }
            }
        }
        __syncthreads();
    }

    // epilogue
#pragma unroll
    for (int mt = 0; mt < 2; mt++) {
#pragma unroll
        for (int nt = 0; nt < 4; nt++) {
            int col = n0 + wn * 32 + nt * 8 + 2 * tig;
            float b0 = bias ? bias[col] : 0.f;
            float b1 = bias ? bias[col + 1] : 0.f;
            int rt_ = m0 + wm * 32 + mt * 16 + grp;
            float2 v0 = make_float2(acc[mt][nt].x + b0, acc[mt][nt].y + b1);
            float2 v1 = make_float2(acc[mt][nt].z + b0, acc[mt][nt].w + b1);
            if (ACT == 1) {
                v0.x = fmaxf(v0.x, 0.f); v0.y = fmaxf(v0.y, 0.f);
                v1.x = fmaxf(v1.x, 0.f); v1.y = fmaxf(v1.y, 0.f);
            }
            if (rt_ < M)     *(float2*)(C + (size_t)rt_ * Nc + col)       = v0;
            if (rt_ + 8 < M) *(float2*)(C + (size_t)(rt_ + 8) * Nc + col) = v1;
        }
    }
}

// ---------------- per-node attention coefficients ----------------
template <int C>
__global__ void k_alpha(const float* __restrict__ hfeat,
                        const float* __restrict__ a_s, const float* __restrict__ a_d) {
    int warp = (blockIdx.x * blockDim.x + threadIdx.x) >> 5;
    int lane = threadIdx.x & 31;
    if (warp >= NN) return;
    const float* hrow = hfeat + (size_t)warp * 4 * C;
#pragma unroll
    for (int h = 0; h < 4; h++) {
        float ps = 0.f, pd = 0.f;
        for (int c = lane; c < C; c += 32) {
            float v = hrow[h * C + c];
            ps += v * a_s[h * C + c];
            pd += v * a_d[h * C + c];
        }
#pragma unroll
        for (int o = 16; o; o >>= 1) {
            ps += __shfl_xor_sync(0xffffffffu, ps, o);
            pd += __shfl_xor_sync(0xffffffffu, pd, o);
        }
        if (lane == 0) {
            g_as[warp * 4 + h] = ps;
            g_ad[warp * 4 + h] = pd;
        }
    }
}

__device__ __forceinline__ float lrelu(float e) { return e > 0.f ? e : NEG * e; }

// ---------------- fused GAT layer-1 aggregate (C=64 per head, ELU) --------
// Two warps per destination node: warp half h handles heads {2h, 2h+1}
// (128 contiguous output floats). Softmax computed WITHOUT max subtraction
// (mathematically identical; logits are O(1)).
__global__ void k_agg1(const float* __restrict__ hfeat, const float* __restrict__ bias,
                       float* __restrict__ out) {
    int gw = (blockIdx.x * blockDim.x + threadIdx.x) >> 5;
    if (gw >= NN * 2) return;
    int lane = threadIdx.x & 31;
    int d = gw >> 1, half = gw & 1;
    int r0 = g_off[d], r1 = g_off[d + 1];
    float2 ad = ((const float2*)g_ad)[d * 2 + half];
    bool lo = lane < 16;
    const float* hb = hfeat + half * 128 + lane * 4;

    float4 acc = make_float4(0.f, 0.f, 0.f, 0.f);
    float s0 = 0.f, s1 = 0.f;
    for (int i = r0; i < r1; i++) {
        int s = g_srcs[i];
        float2 a = ((const float2*)g_as)[s * 2 + half];
        float w0 = __expf(lrelu(a.x + ad.x)); s0 += w0;
        float w1 = __expf(lrelu(a.y + ad.y)); s1 += w1;
        float w = lo ? w0 : w1;
        float4 v = *(const float4*)(hb + (size_t)s * 256);
        acc.x += v.x * w; acc.y += v.y * w; acc.z += v.z * w; acc.w += v.w * w;
    }
    float inv = lo ? 1.f / (s0 + EPSV) : 1.f / (s1 + EPSV);
    float4 bv = *(const float4*)(bias + half * 128 + lane * 4);
    float4 r;
    r.x = acc.x * inv + bv.x;
    r.y = acc.y * inv + bv.y;
    r.z = acc.z * inv + bv.z;
    r.w = acc.w * inv + bv.w;
    // ELU
    r.x = r.x > 0.f ? r.x : expm1f(r.x);
    r.y = r.y > 0.f ? r.y : expm1f(r.y);
    r.z = r.z > 0.f ? r.z : expm1f(r.z);
    r.w = r.w > 0.f ? r.w : expm1f(r.w);
    *(float4*)(out + (size_t)d * 256 + half * 128 + lane * 4) = r;
}

// ---------------- fused GAT layer-2 aggregate (C=16 per head, no act) -----
__global__ void k_agg2(const float* __restrict__ hfeat, const float* __restrict__ bias,
                       float* __restrict__ out) {
    int warp = (blockIdx.x * blockDim.x + threadIdx.x) >> 5;
    int lane = threadIdx.x & 31;
    if (warp >= NN) return;
    int d = warp;
    int r0 = g_off[d], r1 = g_off[d + 1];
    float4 ad = ((const float4*)g_ad)[d];
    int head = lane >> 3;

    float2 acc = make_float2(0.f, 0.f);
    float s0 = 0.f, s1 = 0.f, s2 = 0.f, s3 = 0.f;
    for (int i = r0; i < r1; i++) {
        int s = g_srcs[i];
        float4 a = ((const float4*)g_as)[s];
        float w0 = __expf(lrelu(a.x + ad.x)); s0 += w0;
        float w1 = __expf(lrelu(a.y + ad.y)); s1 += w1;
        float w2 = __expf(lrelu(a.z + ad.z)); s2 += w2;
        float w3 = __expf(lrelu(a.w + ad.w)); s3 += w3;
        float wm = head == 0 ? w0 : head == 1 ? w1 : head == 2 ? w2 : w3;
        float2 v = ((const float2*)(hfeat + (size_t)s * 64))[lane];
        acc.x += v.x * wm;
        acc.y += v.y * wm;
    }
    float im = head == 0 ? 1.f / (s0 + EPSV) : head == 1 ? 1.f / (s1 + EPSV)
             : head == 2 ? 1.f / (s2 + EPSV) : 1.f / (s3 + EPSV);
    float2 bv = ((const float2*)bias)[lane];
    float2 r;
    r.x = acc.x * im + bv.x;
    r.y = acc.y * im + bv.y;
    ((float2*)(out + (size_t)d * 64))[lane] = r;
}

// ---------------- decoder final layer [N,64] @ [64,4] ----------------
__global__ void k_dec2(const float* __restrict__ w2, const float* __restrict__ b2,
                       float* __restrict__ out) {
    int warp = (blockIdx.x * blockDim.x + threadIdx.x) >> 5;
    int lane = threadIdx.x & 31;
    if (warp >= NN) return;
    const float* mid = g_mid + (size_t)warp * 64;
    float4 acc = make_float4(0.f, 0.f, 0.f, 0.f);
#pragma unroll
    for (int k = lane; k < 64; k += 32) {
        float m = mid[k];
        float4 wv = ((const float4*)w2)[k];
        acc.x += m * wv.x; acc.y += m * wv.y;
        acc.z += m * wv.z; acc.w += m * wv.w;
    }
#pragma unroll
    for (int o = 16; o; o >>= 1) {
        acc.x += __shfl_xor_sync(0xffffffffu, acc.x, o);
        acc.y += __shfl_xor_sync(0xffffffffu, acc.y, o);
        acc.z += __shfl_xor_sync(0xffffffffu, acc.z, o);
        acc.w += __shfl_xor_sync(0xffffffffu, acc.w, o);
    }
    if (lane == 0) {
        out[warp * 4 + 0] = acc.x + b2[0];
        out[warp * 4 + 1] = acc.y + b2[1];
        out[warp * 4 + 2] = acc.z + b2[2];
        out[warp * 4 + 3] = acc.w + b2[3];
    }
}

// ---------------- launch ----------------
extern "C" void kernel_launch(void* const* d_in, const int* in_sizes, int n_in,
                              void* d_out, int out_size) {
    const float* x      = (const float*)d_in[0];
    const int*   ei     = (const int*)  d_in[1];
    const float* enc_w1 = (const float*)d_in[2];
    const float* enc_b1 = (const float*)d_in[3];
    const float* enc_w2 = (const float*)d_in[4];
    const float* enc_b2 = (const float*)d_in[5];
    const float* g1_w   = (const float*)d_in[6];
    const float* g1_as  = (const float*)d_in[7];
    const float* g1_ad  = (const float*)d_in[8];
    const float* g1_b   = (const float*)d_in[9];
    const float* g2_w   = (const float*)d_in[10];
    const float* g2_as  = (const float*)d_in[11];
    const float* g2_ad  = (const float*)d_in[12];
    const float* g2_b   = (const float*)d_in[13];
    const float* dec_w1 = (const float*)d_in[14];
    const float* dec_b1 = (const float*)d_in[15];
    const float* dec_w2 = (const float*)d_in[16];
    const float* dec_b2 = (const float*)d_in[17];
    float* out = (float*)d_out;

    float *mid, *h0, *h1, *o1, *h2, *o2;
    cudaGetSymbolAddress((void**)&mid, g_mid);
    cudaGetSymbolAddress((void**)&h0,  g_h0);
    cudaGetSymbolAddress((void**)&h1,  g_h1);
    cudaGetSymbolAddress((void**)&o1,  g_o1);
    cudaGetSymbolAddress((void**)&h2,  g_h2);
    cudaGetSymbolAddress((void**)&o2,  g_o2);

    const int WPB = 6250;      // 50000 warps / 8 warps-per-block
    const int GY  = (NN + 127) / 128;

    // CSR build
    k_zero_deg<<<(NN + 255) / 256, 256>>>();
    k_count<<<(ETOT + 255) / 256, 256>>>(ei);
    k_bsum<<<NB1, 1024>>>();
    k_bscan<<<1, 64>>>();
    k_swrite<<<NB1, 1024>>>();
    k_scatter<<<(ETOT + 255) / 256, 256>>>(ei);

    // encoder
    k_enc1<<<(NN * 64 + 255) / 256, 256>>>(x, enc_w1, enc_b1);
    k_mma_gemm<0><<<dim3(1, GY), 256>>>(mid, enc_w2, enc_b2, h0, NN, 64, 64);

    // GAT layer 1 (C=64, concat->256, ELU)
    k_mma_gemm<0><<<dim3(4, GY), 256>>>(h0, g1_w, nullptr, h1, NN, 64, 256);
    k_alpha<64><<<WPB, 256>>>(h1, g1_as, g1_ad);
    k_agg1<<<(NN * 2 + 7) / 8, 256>>>(h1, g1_b, o1);

    // GAT layer 2 (C=16, concat->64, no act)
    k_mma_gemm<0><<<dim3(1, GY), 256>>>(o1, g2_w, nullptr, h2, NN, 256, 64);
    k_alpha<16><<<WPB, 256>>>(h2, g2_as, g2_ad);
    k_agg2<<<WPB, 256>>>(h2, g2_b, o2);

    // decoder
    k_mma_gemm<1><<<dim3(1, GY), 256>>>(o2, dec_w1, dec_b1, mid, NN, 64, 64);
    k_dec2<<<WPB, 256>>>(dec_w2, dec_b2, out);
}

// round 3
// speedup vs baseline: 1.5844x; 1.0845x over previous
#include <cuda_runtime.h>
#include <math.h>
#include <stdint.h>

#define NN 50000
#define NE 800000
#define ETOT (NE + NN)
#define NEG 0.2f
#define EPSV 1e-16f
#define NB1 49   // ceil(NN/1024)

// ---------------- scratch (device globals; no allocation allowed) ----------
__device__ __align__(16) float g_mid[NN * 64];
__device__ __align__(16) float g_h0 [NN * 64];
__device__ __align__(16) float g_h1 [NN * 256];
__device__ __align__(16) float g_o1 [NN * 256];
__device__ __align__(16) float g_h2 [NN * 64];
__device__ __align__(16) float g_o2 [NN * 64];
__device__ __align__(16) float g_as [NN * 4];
__device__ __align__(16) float g_ad [NN * 4];
__device__ __align__(16) float g_was[256];
__device__ __align__(16) float g_wad[256];
__device__ int g_deg[NN];
__device__ int g_off[NN + 1];
__device__ int g_cur[NN];
__device__ int g_srcs[ETOT];
__device__ int g_bsum[NB1];
__device__ int g_boff[NB1];

// ---------------- CSR build ----------------
__global__ void k_zero_deg() {
    int i = blockIdx.x * blockDim.x + threadIdx.x;
    if (i < NN) g_deg[i] = 0;
}

__global__ void k_count(const int* __restrict__ ei) {
    int i = blockIdx.x * blockDim.x + threadIdx.x;
    if (i >= ETOT) return;
    int d = (i < NE) ? ei[NE + i] : (i - NE);
    atomicAdd(&g_deg[d], 1);
}

__global__ void k_bsum() {
    __shared__ int sh[1024];
    int t = threadIdx.x;
    int i = blockIdx.x * 1024 + t;
    sh[t] = (i < NN) ? g_deg[i] : 0;
    __syncthreads();
#pragma unroll
    for (int o = 512; o > 0; o >>= 1) {
        if (t < o) sh[t] += sh[t + o];
        __syncthreads();
    }
    if (t == 0) g_bsum[blockIdx.x] = sh[0];
}

__global__ void k_bscan() {
    __shared__ int sh[64];
    int t = threadIdx.x;
    int v = (t < NB1) ? g_bsum[t] : 0;
    sh[t] = v;
    __syncthreads();
#pragma unroll
    for (int o = 1; o < 64; o <<= 1) {
        int x = (t >= o) ? sh[t - o] : 0;
        __syncthreads();
        sh[t] += x;
        __syncthreads();
    }
    if (t < NB1) g_boff[t] = sh[t] - v;
}

__global__ void k_swrite() {
    __shared__ int sh[1024];
    int t = threadIdx.x;
    int i = blockIdx.x * 1024 + t;
    int v = (i < NN) ? g_deg[i] : 0;
    sh[t] = v;
    __syncthreads();
#pragma unroll
    for (int o = 1; o < 1024; o <<= 1) {
        int x = (t >= o) ? sh[t - o] : 0;
        __syncthreads();
        sh[t] += x;
        __syncthreads();
    }
    int incl = sh[t];
    int base = g_boff[blockIdx.x];
    if (i < NN) {
        int off = base + incl - v;
        g_off[i] = off;
        g_cur[i] = off;
        if (i == NN - 1) g_off[NN] = base + incl;
    }
}

__global__ void k_scatter(const int* __restrict__ ei) {
    int i = blockIdx.x * blockDim.x + threadIdx.x;
    if (i >= ETOT) return;
    int s, d;
    if (i < NE) { s = ei[i]; d = ei[NE + i]; }
    else        { s = i - NE; d = i - NE; }
    int p = atomicAdd(&g_cur[d], 1);
    g_srcs[p] = s;
}

// ---------------- encoder first layer (K=7) ----------------
__global__ void k_enc1(const float* __restrict__ x, const float* __restrict__ w1,
                       const float* __restrict__ b1) {
    int idx = blockIdx.x * blockDim.x + threadIdx.x;
    if (idx >= NN * 64) return;
    int n = idx >> 6, c = idx & 63;
    float s = b1[c];
#pragma unroll
    for (int k = 0; k < 7; k++) s += x[n * 7 + k] * w1[k * 64 + c];
    g_mid[idx] = fmaxf(s, 0.f);
}

// ---------------- tf32 tensor-core GEMM (3xTF32 split) ----------------
__device__ __forceinline__ float tf32_rn(float x) {
    uint32_t u;
    asm("cvt.rna.tf32.f32 %0, %1;" : "=r"(u) : "f"(x));
    return __uint_as_float(u);
}

__device__ __forceinline__ void mma_tf32(float4& d, const uint32_t a[4], const uint32_t b[2]) {
    asm volatile(
        "mma.sync.aligned.m16n8k8.row.col.f32.tf32.tf32.f32 "
        "{%0,%1,%2,%3},{%4,%5,%6,%7},{%8,%9},{%0,%1,%2,%3};\n"
        : "+f"(d.x), "+f"(d.y), "+f"(d.z), "+f"(d.w)
        : "r"(a[0]), "r"(a[1]), "r"(a[2]), "r"(a[3]), "r"(b[0]), "r"(b[1]));
}

template <int ACT>  // 0 none, 1 relu
__global__ void k_mma_gemm(const float* __restrict__ A, const float* __restrict__ B,
                           const float* __restrict__ bias, float* __restrict__ C,
                           int M, int K, int Nc) {
    __shared__ float Ah[16][136], Al[16][136];
    __shared__ float Bh[16][72],  Bl[16][72];

    int tid  = threadIdx.x;
    int warp = tid >> 5, lane = tid & 31;
    int wm = warp >> 1, wn = warp & 1;
    int m0 = blockIdx.y * 128, n0 = blockIdx.x * 64;
    int grp = lane >> 2, tig = lane & 3;

    float4 acc[2][4];
#pragma unroll
    for (int i = 0; i < 2; i++)
#pragma unroll
        for (int j = 0; j < 4; j++) acc[i][j] = make_float4(0.f, 0.f, 0.f, 0.f);

    for (int k0 = 0; k0 < K; k0 += 16) {
#pragma unroll
        for (int r = 0; r < 2; r++) {
            int idx = tid + 256 * r;
            int m = idx >> 2, kq = idx & 3;
            int row = m0 + m;
            float4 v = make_float4(0.f, 0.f, 0.f, 0.f);
            if (row < M) v = *(const float4*)(A + (size_t)row * K + k0 + 4 * kq);
            float h;
            h = tf32_rn(v.x); Ah[4*kq+0][m] = h; Al[4*kq+0][m] = tf32_rn(v.x - h);
            h = tf32_rn(v.y); Ah[4*kq+1][m] = h; Al[4*kq+1][m] = tf32_rn(v.y - h);
            h = tf32_rn(v.z); Ah[4*kq+2][m] = h; Al[4*kq+2][m] = tf32_rn(v.z - h);
            h = tf32_rn(v.w); Ah[4*kq+3][m] = h; Al[4*kq+3][m] = tf32_rn(v.w - h);
        }
        {
            int kk = tid >> 4, nq = tid & 15;
            float4 v = *(const float4*)(B + (size_t)(k0 + kk) * Nc + n0 + 4 * nq);
            float4 hv, lv;
            hv.x = tf32_rn(v.x); lv.x = tf32_rn(v.x - hv.x);
            hv.y = tf32_rn(v.y); lv.y = tf32_rn(v.y - hv.y);
            hv.z = tf32_rn(v.z); lv.z = tf32_rn(v.z - hv.z);
            hv.w = tf32_rn(v.w); lv.w = tf32_rn(v.w - hv.w);
            *(float4*)&Bh[kk][4 * nq] = hv;
            *(float4*)&Bl[kk][4 * nq] = lv;
        }
        __syncthreads();

#pragma unroll
        for (int ks = 0; ks < 2; ks++) {
            int kb = ks * 8;
            uint32_t aH[2][4], aL[2][4];
#pragma unroll
            for (int mt = 0; mt < 2; mt++) {
                int mb = wm * 32 + mt * 16 + grp;
                aH[mt][0] = __float_as_uint(Ah[kb + tig    ][mb]);
                aH[mt][1] = __float_as_uint(Ah[kb + tig    ][mb + 8]);
                aH[mt][2] = __float_as_uint(Ah[kb + tig + 4][mb]);
                aH[mt][3] = __float_as_uint(Ah[kb + tig + 4][mb + 8]);
                aL[mt][0] = __float_as_uint(Al[kb + tig    ][mb]);
                aL[mt][1] = __float_as_uint(Al[kb + tig    ][mb + 8]);
                aL[mt][2] = __float_as_uint(Al[kb + tig + 4][mb]);
                aL[mt][3] = __float_as_uint(Al[kb + tig + 4][mb + 8]);
            }
#pragma unroll
            for (int nt = 0; nt < 4; nt++) {
                int nb = wn * 32 + nt * 8 + grp;
                uint32_t bH[2], bL[2];
                bH[0] = __float_as_uint(Bh[kb + tig    ][nb]);
                bH[1] = __float_as_uint(Bh[kb + tig + 4][nb]);
                bL[0] = __float_as_uint(Bl[kb + tig    ][nb]);
                bL[1] = __float_as_uint(Bl[kb + tig + 4][nb]);
#pragma unroll
                for (int mt = 0; mt < 2; mt++) {
                    mma_tf32(acc[mt][nt], aH[mt], bH);
                    mma_tf32(acc[mt][nt], aL[mt], bH);
                    mma_tf32(acc[mt][nt], aH[mt], bL);
                }
            }
        }
        __syncthreads();
    }

#pragma unroll
    for (int mt = 0; mt < 2; mt++) {
#pragma unroll
        for (int nt = 0; nt < 4; nt++) {
            int col = n0 + wn * 32 + nt * 8 + 2 * tig;
            float b0 = bias ? bias[col] : 0.f;
            float b1 = bias ? bias[col + 1] : 0.f;
            int rt_ = m0 + wm * 32 + mt * 16 + grp;
            float2 v0 = make_float2(acc[mt][nt].x + b0, acc[mt][nt].y + b1);
            float2 v1 = make_float2(acc[mt][nt].z + b0, acc[mt][nt].w + b1);
            if (ACT == 1) {
                v0.x = fmaxf(v0.x, 0.f); v0.y = fmaxf(v0.y, 0.f);
                v1.x = fmaxf(v1.x, 0.f); v1.y = fmaxf(v1.y, 0.f);
            }
            if (rt_ < M)     *(float2*)(C + (size_t)rt_ * Nc + col)       = v0;
            if (rt_ + 8 < M) *(float2*)(C + (size_t)(rt_ + 8) * Nc + col) = v1;
        }
    }
}

// ---------------- fold g1_w with attention vectors: waS/waD [64][4] -------
__global__ void k_fold1(const float* __restrict__ w, const float* __restrict__ as_,
                        const float* __restrict__ ad_) {
    int t = threadIdx.x;          // 256 threads: t = k*4 + h
    int k = t >> 2, h = t & 3;
    float s = 0.f, d = 0.f;
#pragma unroll
    for (int c = 0; c < 64; c++) {
        float v = w[k * 256 + h * 64 + c];
        s += v * as_[h * 64 + c];
        d += v * ad_[h * 64 + c];
    }
    g_was[t] = s;
    g_wad[t] = d;
}

// ---------------- alpha for layer 1: from h0 via folded weights -----------
__global__ void k_alpha1(const float* __restrict__ h0f) {
    int warp = (blockIdx.x * blockDim.x + threadIdx.x) >> 5;
    int lane = threadIdx.x & 31;
    if (warp >= NN) return;
    float v1 = h0f[(size_t)warp * 64 + lane];
    float v2 = h0f[(size_t)warp * 64 + lane + 32];
    float4 wsA = ((const float4*)g_was)[lane];
    float4 wsB = ((const float4*)g_was)[lane + 32];
    float4 wdA = ((const float4*)g_wad)[lane];
    float4 wdB = ((const float4*)g_wad)[lane + 32];
    float4 ps, pd;
    ps.x = v1 * wsA.x + v2 * wsB.x; ps.y = v1 * wsA.y + v2 * wsB.y;
    ps.z = v1 * wsA.z + v2 * wsB.z; ps.w = v1 * wsA.w + v2 * wsB.w;
    pd.x = v1 * wdA.x + v2 * wdB.x; pd.y = v1 * wdA.y + v2 * wdB.y;
    pd.z = v1 * wdA.z + v2 * wdB.z; pd.w = v1 * wdA.w + v2 * wdB.w;
#pragma unroll
    for (int o = 16; o; o >>= 1) {
        ps.x += __shfl_xor_sync(0xffffffffu, ps.x, o);
        ps.y += __shfl_xor_sync(0xffffffffu, ps.y, o);
        ps.z += __shfl_xor_sync(0xffffffffu, ps.z, o);
        ps.w += __shfl_xor_sync(0xffffffffu, ps.w, o);
        pd.x += __shfl_xor_sync(0xffffffffu, pd.x, o);
        pd.y += __shfl_xor_sync(0xffffffffu, pd.y, o);
        pd.z += __shfl_xor_sync(0xffffffffu, pd.z, o);
        pd.w += __shfl_xor_sync(0xffffffffu, pd.w, o);
    }
    if (lane == 0) {
        ((float4*)g_as)[warp] = ps;
        ((float4*)g_ad)[warp] = pd;
    }
}

// ---------------- alpha for layer 2: directly from h2 (C=16) --------------
__global__ void k_alpha2(const float* __restrict__ h2f, const float* __restrict__ as_,
                         const float* __restrict__ ad_) {
    int warp = (blockIdx.x * blockDim.x + threadIdx.x) >> 5;
    int lane = threadIdx.x & 31;
    if (warp >= NN) return;
    float v1 = h2f[(size_t)warp * 64 + lane];        // heads 0,1
    float v2 = h2f[(size_t)warp * 64 + lane + 32];   // heads 2,3
    float sA = v1 * as_[lane],      dA = v1 * ad_[lane];
    float sB = v2 * as_[32 + lane], dB = v2 * ad_[32 + lane];
#pragma unroll
    for (int o = 8; o; o >>= 1) {                    // segmented reduce (16)
        sA += __shfl_xor_sync(0xffffffffu, sA, o);
        sB += __shfl_xor_sync(0xffffffffu, sB, o);
        dA += __shfl_xor_sync(0xffffffffu, dA, o);
        dB += __shfl_xor_sync(0xffffffffu, dB, o);
    }
    if ((lane & 15) == 0) {
        int hb = lane >> 4;   // 0 or 1
        g_as[warp * 4 + hb]     = sA;
        g_as[warp * 4 + hb + 2] = sB;
        g_ad[warp * 4 + hb]     = dA;
        g_ad[warp * 4 + hb + 2] = dB;
    }
}

__device__ __forceinline__ float lrelu(float e) { return e > 0.f ? e : NEG * e; }

// ---------------- fused GAT layer-1 aggregate (C=64/head, ELU) ------------
// Two warps per node (half = head pair). Lane-parallel weight computation,
// smem-broadcast gather. No max subtraction (mathematically identical).
__global__ void k_agg1(const float* __restrict__ hfeat, const float* __restrict__ bias,
                       float* __restrict__ out) {
    __shared__ float4 sh_w[8][32];
    int gw = (blockIdx.x * blockDim.x + threadIdx.x) >> 5;
    if (gw >= NN * 2) return;
    int lane = threadIdx.x & 31;
    int wip = threadIdx.x >> 5;
    int d = gw >> 1, half = gw & 1;
    int r0 = g_off[d], deg = g_off[d + 1] - r0;
    float2 ad = ((const float2*)g_ad)[d * 2 + half];
    bool lo = lane < 16;
    const float* hb = hfeat + half * 128 + lane * 4;

    float4 acc = make_float4(0.f, 0.f, 0.f, 0.f);
    float s0 = 0.f, s1 = 0.f;
    for (int base = 0; base < deg; base += 32) {
        int n = deg - base; if (n > 32) n = 32;
        float w0 = 0.f, w1 = 0.f; int s = 0;
        if (lane < n) {
            s = g_srcs[r0 + base + lane];
            float2 a = ((const float2*)g_as)[s * 2 + half];
            w0 = __expf(lrelu(a.x + ad.x));
            w1 = __expf(lrelu(a.y + ad.y));
        }
        s0 += w0; s1 += w1;
        sh_w[wip][lane] = make_float4(__int_as_float(s), w0, w1, 0.f);
        __syncwarp();
#pragma unroll 4
        for (int j = 0; j < n; j++) {
            float4 t = sh_w[wip][j];
            int sj = __float_as_int(t.x);
            float wj = lo ? t.y : t.z;
            float4 v = *(const float4*)(hb + (size_t)sj * 256);
            acc.x += v.x * wj; acc.y += v.y * wj;
            acc.z += v.z * wj; acc.w += v.w * wj;
        }
        __syncwarp();
    }
#pragma unroll
    for (int o = 16; o; o >>= 1) {
        s0 += __shfl_xor_sync(0xffffffffu, s0, o);
        s1 += __shfl_xor_sync(0xffffffffu, s1, o);
    }
    float inv = lo ? 1.f / (s0 + EPSV) : 1.f / (s1 + EPSV);
    float4 bv = *(const float4*)(bias + half * 128 + lane * 4);
    float4 r;
    r.x = acc.x * inv + bv.x;
    r.y = acc.y * inv + bv.y;
    r.z = acc.z * inv + bv.z;
    r.w = acc.w * inv + bv.w;
    r.x = r.x > 0.f ? r.x : expm1f(r.x);
    r.y = r.y > 0.f ? r.y : expm1f(r.y);
    r.z = r.z > 0.f ? r.z : expm1f(r.z);
    r.w = r.w > 0.f ? r.w : expm1f(r.w);
    *(float4*)(out + (size_t)d * 256 + half * 128 + lane * 4) = r;
}

// ---------------- fused GAT layer-2 aggregate (C=16/head, no act) ---------
__global__ void k_agg2(const float* __restrict__ hfeat, const float* __restrict__ bias,
                       float* __restrict__ out) {
    __shared__ float4 sh_w[8][32];
    __shared__ int    sh_s[8][32];
    int warp = (blockIdx.x * blockDim.x + threadIdx.x) >> 5;
    int lane = threadIdx.x & 31;
    if (warp >= NN) return;
    int wip = threadIdx.x >> 5;
    int d = warp;
    int r0 = g_off[d], deg = g_off[d + 1] - r0;
    float4 adv = ((const float4*)g_ad)[d];
    int head = lane >> 3;

    float2 acc = make_float2(0.f, 0.f);
    float s0 = 0.f, s1 = 0.f, s2 = 0.f, s3 = 0.f;
    for (int base = 0; base < deg; base += 32) {
        int n = deg - base; if (n > 32) n = 32;
        float4 w = make_float4(0.f, 0.f, 0.f, 0.f); int s = 0;
        if (lane < n) {
            s = g_srcs[r0 + base + lane];
            float4 a = ((const float4*)g_as)[s];
            w.x = __expf(lrelu(a.x + adv.x));
            w.y = __expf(lrelu(a.y + adv.y));
            w.z = __expf(lrelu(a.z + adv.z));
            w.w = __expf(lrelu(a.w + adv.w));
        }
        s0 += w.x; s1 += w.y; s2 += w.z; s3 += w.w;
        sh_w[wip][lane] = w;
        sh_s[wip][lane] = s;
        __syncwarp();
#pragma unroll 4
        for (int j = 0; j < n; j++) {
            float4 wv = sh_w[wip][j];
            int sj = sh_s[wip][j];
            float wm = head == 0 ? wv.x : head == 1 ? wv.y : head == 2 ? wv.z : wv.w;
            float2 v = ((const float2*)(hfeat + (size_t)sj * 64))[lane];
            acc.x += v.x * wm;
            acc.y += v.y * wm;
        }
        __syncwarp();
    }
#pragma unroll
    for (int o = 16; o; o >>= 1) {
        s0 += __shfl_xor_sync(0xffffffffu, s0, o);
        s1 += __shfl_xor_sync(0xffffffffu, s1, o);
        s2 += __shfl_xor_sync(0xffffffffu, s2, o);
        s3 += __shfl_xor_sync(0xffffffffu, s3, o);
    }
    float im = head == 0 ? 1.f / (s0 + EPSV) : head == 1 ? 1.f / (s1 + EPSV)
             : head == 2 ? 1.f / (s2 + EPSV) : 1.f / (s3 + EPSV);
    float2 bv = ((const float2*)bias)[lane];
    float2 r;
    r.x = acc.x * im + bv.x;
    r.y = acc.y * im + bv.y;
    ((float2*)(out + (size_t)d * 64))[lane] = r;
}

// ---------------- decoder final layer [N,64] @ [64,4] ----------------
__global__ void k_dec2(const float* __restrict__ w2, const float* __restrict__ b2,
                       float* __restrict__ out) {
    int warp = (blockIdx.x * blockDim.x + threadIdx.x) >> 5;
    int lane = threadIdx.x & 31;
    if (warp >= NN) return;
    const float* mid = g_mid + (size_t)warp * 64;
    float4 acc = make_float4(0.f, 0.f, 0.f, 0.f);
#pragma unroll
    for (int k = lane; k < 64; k += 32) {
        float m = mid[k];
        float4 wv = ((const float4*)w2)[k];
        acc.x += m * wv.x; acc.y += m * wv.y;
        acc.z += m * wv.z; acc.w += m * wv.w;
    }
#pragma unroll
    for (int o = 16; o; o >>= 1) {
        acc.x += __shfl_xor_sync(0xffffffffu, acc.x, o);
        acc.y += __shfl_xor_sync(0xffffffffu, acc.y, o);
        acc.z += __shfl_xor_sync(0xffffffffu, acc.z, o);
        acc.w += __shfl_xor_sync(0xffffffffu, acc.w, o);
    }
    if (lane == 0) {
        out[warp * 4 + 0] = acc.x + b2[0];
        out[warp * 4 + 1] = acc.y + b2[1];
        out[warp * 4 + 2] = acc.z + b2[2];
        out[warp * 4 + 3] = acc.w + b2[3];
    }
}

// ---------------- launch ----------------
extern "C" void kernel_launch(void* const* d_in, const int* in_sizes, int n_in,
                              void* d_out, int out_size) {
    const float* x      = (const float*)d_in[0];
    const int*   ei     = (const int*)  d_in[1];
    const float* enc_w1 = (const float*)d_in[2];
    const float* enc_b1 = (const float*)d_in[3];
    const float* enc_w2 = (const float*)d_in[4];
    const float* enc_b2 = (const float*)d_in[5];
    const float* g1_w   = (const float*)d_in[6];
    const float* g1_as  = (const float*)d_in[7];
    const float* g1_ad  = (const float*)d_in[8];
    const float* g1_b   = (const float*)d_in[9];
    const float* g2_w   = (const float*)d_in[10];
    const float* g2_as  = (const float*)d_in[11];
    const float* g2_ad  = (const float*)d_in[12];
    const float* g2_b   = (const float*)d_in[13];
    const float* dec_w1 = (const float*)d_in[14];
    const float* dec_b1 = (const float*)d_in[15];
    const float* dec_w2 = (const float*)d_in[16];
    const float* dec_b2 = (const float*)d_in[17];
    float* out = (float*)d_out;

    float *mid, *h0, *h1, *o1, *h2, *o2;
    cudaGetSymbolAddress((void**)&mid, g_mid);
    cudaGetSymbolAddress((void**)&h0,  g_h0);
    cudaGetSymbolAddress((void**)&h1,  g_h1);
    cudaGetSymbolAddress((void**)&o1,  g_o1);
    cudaGetSymbolAddress((void**)&h2,  g_h2);
    cudaGetSymbolAddress((void**)&o2,  g_o2);

    const int WPB = 6250;      // 50000 warps / 8 warps-per-block
    const int GY  = (NN + 127) / 128;

    // CSR build
    k_zero_deg<<<(NN + 255) / 256, 256>>>();
    k_count<<<(ETOT + 255) / 256, 256>>>(ei);
    k_bsum<<<NB1, 1024>>>();
    k_bscan<<<1, 64>>>();
    k_swrite<<<NB1, 1024>>>();
    k_scatter<<<(ETOT + 255) / 256, 256>>>(ei);

    // encoder
    k_enc1<<<(NN * 64 + 255) / 256, 256>>>(x, enc_w1, enc_b1);
    k_mma_gemm<0><<<dim3(1, GY), 256>>>(mid, enc_w2, enc_b2, h0, NN, 64, 64);

    // GAT layer 1 (C=64, concat->256, ELU)
    k_fold1<<<1, 256>>>(g1_w, g1_as, g1_ad);
    k_alpha1<<<WPB, 256>>>(h0);
    k_mma_gemm<0><<<dim3(4, GY), 256>>>(h0, g1_w, nullptr, h1, NN, 64, 256);
    k_agg1<<<(NN * 2 + 7) / 8, 256>>>(h1, g1_b, o1);

    // GAT layer 2 (C=16, concat->64, no act)
    k_mma_gemm<0><<<dim3(1, GY), 256>>>(o1, g2_w, nullptr, h2, NN, 256, 64);
    k_alpha2<<<WPB, 256>>>(h2, g2_as, g2_ad);
    k_agg2<<<WPB, 256>>>(h2, g2_b, o2);

    // decoder
    k_mma_gemm<1><<<dim3(1, GY), 256>>>(o2, dec_w1, dec_b1, mid, NN, 64, 64);
    k_dec2<<<WPB, 256>>>(dec_w2, dec_b2, out);
}

// round 4
// speedup vs baseline: 1.7815x; 1.1244x over previous
#include <cuda_runtime.h>
#include <math.h>
#include <stdint.h>

#define NN 50000
#define NE 800000
#define ETOT (NE + NN)
#define NEG 0.2f
#define EPSV 1e-16f
#define NB1 49   // ceil(NN/1024)

// ---------------- scratch (device globals; no allocation allowed) ----------
__device__ __align__(16) float g_mid[NN * 64];
__device__ __align__(16) float g_h0 [NN * 64];
__device__ __align__(16) float g_agg[NN * 256];   // layer-1 aggregated h0 (per head)
__device__ __align__(16) float g_o1 [NN * 256];
__device__ __align__(16) float g_h2 [NN * 64];
__device__ __align__(16) float g_o2 [NN * 64];
__device__ __align__(16) float g_as [NN * 4];
__device__ __align__(16) float g_ad [NN * 4];
__device__ __align__(16) float g_was[256];
__device__ __align__(16) float g_wad[256];
__device__ int g_deg[NN];
__device__ int g_off[NN + 1];
__device__ int g_cur[NN];
__device__ int g_srcs[ETOT];
__device__ int g_bsum[NB1];
__device__ int g_boff[NB1];

// ---------------- CSR build ----------------
__global__ void k_zero_deg() {
    int i = blockIdx.x * blockDim.x + threadIdx.x;
    if (i < NN) g_deg[i] = 0;
}

__global__ void k_count(const int* __restrict__ ei) {
    int i = blockIdx.x * blockDim.x + threadIdx.x;
    if (i >= ETOT) return;
    int d = (i < NE) ? ei[NE + i] : (i - NE);
    atomicAdd(&g_deg[d], 1);
}

__global__ void k_bsum() {
    __shared__ int sh[1024];
    int t = threadIdx.x;
    int i = blockIdx.x * 1024 + t;
    sh[t] = (i < NN) ? g_deg[i] : 0;
    __syncthreads();
#pragma unroll
    for (int o = 512; o > 0; o >>= 1) {
        if (t < o) sh[t] += sh[t + o];
        __syncthreads();
    }
    if (t == 0) g_bsum[blockIdx.x] = sh[0];
}

__global__ void k_bscan() {
    __shared__ int sh[64];
    int t = threadIdx.x;
    int v = (t < NB1) ? g_bsum[t] : 0;
    sh[t] = v;
    __syncthreads();
#pragma unroll
    for (int o = 1; o < 64; o <<= 1) {
        int x = (t >= o) ? sh[t - o] : 0;
        __syncthreads();
        sh[t] += x;
        __syncthreads();
    }
    if (t < NB1) g_boff[t] = sh[t] - v;
}

__global__ void k_swrite() {
    __shared__ int sh[1024];
    int t = threadIdx.x;
    int i = blockIdx.x * 1024 + t;
    int v = (i < NN) ? g_deg[i] : 0;
    sh[t] = v;
    __syncthreads();
#pragma unroll
    for (int o = 1; o < 1024; o <<= 1) {
        int x = (t >= o) ? sh[t - o] : 0;
        __syncthreads();
        sh[t] += x;
        __syncthreads();
    }
    int incl = sh[t];
    int base = g_boff[blockIdx.x];
    if (i < NN) {
        int off = base + incl - v;
        g_off[i] = off;
        g_cur[i] = off;
        if (i == NN - 1) g_off[NN] = base + incl;
    }
}

__global__ void k_scatter(const int* __restrict__ ei) {
    int i = blockIdx.x * blockDim.x + threadIdx.x;
    if (i >= ETOT) return;
    int s, d;
    if (i < NE) { s = ei[i]; d = ei[NE + i]; }
    else        { s = i - NE; d = i - NE; }
    int p = atomicAdd(&g_cur[d], 1);
    g_srcs[p] = s;
}

// ---------------- encoder first layer (K=7) ----------------
__global__ void k_enc1(const float* __restrict__ x, const float* __restrict__ w1,
                       const float* __restrict__ b1) {
    int idx = blockIdx.x * blockDim.x + threadIdx.x;
    if (idx >= NN * 64) return;
    int n = idx >> 6, c = idx & 63;
    float s = b1[c];
#pragma unroll
    for (int k = 0; k < 7; k++) s += x[n * 7 + k] * w1[k * 64 + c];
    g_mid[idx] = fmaxf(s, 0.f);
}

// ---------------- tf32 tensor-core GEMM (3xTF32 split) ----------------
// C[M,Nc] = A[M,K] @ B[K,Nc] (+bias, act), strided (lda/ldb/ldc),
// blockIdx.z batching with column offset zoff per z (A, B, C, bias all shift).
// ACT: 0 none, 1 relu, 2 elu.
__device__ __forceinline__ float tf32_rn(float x) {
    uint32_t u;
    asm("cvt.rna.tf32.f32 %0, %1;" : "=r"(u) : "f"(x));
    return __uint_as_float(u);
}

__device__ __forceinline__ void mma_tf32(float4& d, const uint32_t a[4], const uint32_t b[2]) {
    asm volatile(
        "mma.sync.aligned.m16n8k8.row.col.f32.tf32.tf32.f32 "
        "{%0,%1,%2,%3},{%4,%5,%6,%7},{%8,%9},{%0,%1,%2,%3};\n"
        : "+f"(d.x), "+f"(d.y), "+f"(d.z), "+f"(d.w)
        : "r"(a[0]), "r"(a[1]), "r"(a[2]), "r"(a[3]), "r"(b[0]), "r"(b[1]));
}

template <int ACT>
__global__ void k_mma_gemm(const float* __restrict__ A, const float* __restrict__ B,
                           const float* __restrict__ bias, float* __restrict__ C,
                           int M, int K, int Nc, int lda, int ldb, int ldc, int zoff) {
    __shared__ float Ah[16][136], Al[16][136];
    __shared__ float Bh[16][72],  Bl[16][72];

    int zo = blockIdx.z * zoff;
    A += zo; B += zo; C += zo;
    if (bias) bias += zo;

    int tid  = threadIdx.x;
    int warp = tid >> 5, lane = tid & 31;
    int wm = warp >> 1, wn = warp & 1;
    int m0 = blockIdx.y * 128, n0 = blockIdx.x * 64;
    int grp = lane >> 2, tig = lane & 3;

    float4 acc[2][4];
#pragma unroll
    for (int i = 0; i < 2; i++)
#pragma unroll
        for (int j = 0; j < 4; j++) acc[i][j] = make_float4(0.f, 0.f, 0.f, 0.f);

    for (int k0 = 0; k0 < K; k0 += 16) {
#pragma unroll
        for (int r = 0; r < 2; r++) {
            int idx = tid + 256 * r;
            int m = idx >> 2, kq = idx & 3;
            int row = m0 + m;
            float4 v = make_float4(0.f, 0.f, 0.f, 0.f);
            if (row < M) v = *(const float4*)(A + (size_t)row * lda + k0 + 4 * kq);
            float h;
            h = tf32_rn(v.x); Ah[4*kq+0][m] = h; Al[4*kq+0][m] = tf32_rn(v.x - h);
            h = tf32_rn(v.y); Ah[4*kq+1][m] = h; Al[4*kq+1][m] = tf32_rn(v.y - h);
            h = tf32_rn(v.z); Ah[4*kq+2][m] = h; Al[4*kq+2][m] = tf32_rn(v.z - h);
            h = tf32_rn(v.w); Ah[4*kq+3][m] = h; Al[4*kq+3][m] = tf32_rn(v.w - h);
        }
        {
            int kk = tid >> 4, nq = tid & 15;
            float4 v = *(const float4*)(B + (size_t)(k0 + kk) * ldb + n0 + 4 * nq);
            float4 hv, lv;
            hv.x = tf32_rn(v.x); lv.x = tf32_rn(v.x - hv.x);
            hv.y = tf32_rn(v.y); lv.y = tf32_rn(v.y - hv.y);
            hv.z = tf32_rn(v.z); lv.z = tf32_rn(v.z - hv.z);
            hv.w = tf32_rn(v.w); lv.w = tf32_rn(v.w - hv.w);
            *(float4*)&Bh[kk][4 * nq] = hv;
            *(float4*)&Bl[kk][4 * nq] = lv;
        }
        __syncthreads();

#pragma unroll
        for (int ks = 0; ks < 2; ks++) {
            int kb = ks * 8;
            uint32_t aH[2][4], aL[2][4];
#pragma unroll
            for (int mt = 0; mt < 2; mt++) {
                int mb = wm * 32 + mt * 16 + grp;
                aH[mt][0] = __float_as_uint(Ah[kb + tig    ][mb]);
                aH[mt][1] = __float_as_uint(Ah[kb + tig    ][mb + 8]);
                aH[mt][2] = __float_as_uint(Ah[kb + tig + 4][mb]);
                aH[mt][3] = __float_as_uint(Ah[kb + tig + 4][mb + 8]);
                aL[mt][0] = __float_as_uint(Al[kb + tig    ][mb]);
                aL[mt][1] = __float_as_uint(Al[kb + tig    ][mb + 8]);
                aL[mt][2] = __float_as_uint(Al[kb + tig + 4][mb]);
                aL[mt][3] = __float_as_uint(Al[kb + tig + 4][mb + 8]);
            }
#pragma unroll
            for (int nt = 0; nt < 4; nt++) {
                int nb = wn * 32 + nt * 8 + grp;
                uint32_t bH[2], bL[2];
                bH[0] = __float_as_uint(Bh[kb + tig    ][nb]);
                bH[1] = __float_as_uint(Bh[kb + tig + 4][nb]);
                bL[0] = __float_as_uint(Bl[kb + tig    ][nb]);
                bL[1] = __float_as_uint(Bl[kb + tig + 4][nb]);
#pragma unroll
                for (int mt = 0; mt < 2; mt++) {
                    mma_tf32(acc[mt][nt], aH[mt], bH);
                    mma_tf32(acc[mt][nt], aL[mt], bH);
                    mma_tf32(acc[mt][nt], aH[mt], bL);
                }
            }
        }
        __syncthreads();
    }

#pragma unroll
    for (int mt = 0; mt < 2; mt++) {
#pragma unroll
        for (int nt = 0; nt < 4; nt++) {
            int col = n0 + wn * 32 + nt * 8 + 2 * tig;
            float b0 = bias ? bias[col] : 0.f;
            float b1 = bias ? bias[col + 1] : 0.f;
            int rt_ = m0 + wm * 32 + mt * 16 + grp;
            float2 v0 = make_float2(acc[mt][nt].x + b0, acc[mt][nt].y + b1);
            float2 v1 = make_float2(acc[mt][nt].z + b0, acc[mt][nt].w + b1);
            if (ACT == 1) {
                v0.x = fmaxf(v0.x, 0.f); v0.y = fmaxf(v0.y, 0.f);
                v1.x = fmaxf(v1.x, 0.f); v1.y = fmaxf(v1.y, 0.f);
            } else if (ACT == 2) {
                v0.x = v0.x > 0.f ? v0.x : expm1f(v0.x);
                v0.y = v0.y > 0.f ? v0.y : expm1f(v0.y);
                v1.x = v1.x > 0.f ? v1.x : expm1f(v1.x);
                v1.y = v1.y > 0.f ? v1.y : expm1f(v1.y);
            }
            if (rt_ < M)     *(float2*)(C + (size_t)rt_ * ldc + col)       = v0;
            if (rt_ + 8 < M) *(float2*)(C + (size_t)(rt_ + 8) * ldc + col) = v1;
        }
    }
}

// ---------------- fold g1_w with attention vectors: waS/waD [64][4] -------
__global__ void k_fold1(const float* __restrict__ w, const float* __restrict__ as_,
                        const float* __restrict__ ad_) {
    int t = threadIdx.x;          // 256 threads: t = k*4 + h
    int k = t >> 2, h = t & 3;
    float s = 0.f, d = 0.f;
#pragma unroll
    for (int c = 0; c < 64; c++) {
        float v = w[k * 256 + h * 64 + c];
        s += v * as_[h * 64 + c];
        d += v * ad_[h * 64 + c];
    }
    g_was[t] = s;
    g_wad[t] = d;
}

// ---------------- alpha for layer 1: from h0 via folded weights -----------
__global__ void k_alpha1(const float* __restrict__ h0f) {
    int warp = (blockIdx.x * blockDim.x + threadIdx.x) >> 5;
    int lane = threadIdx.x & 31;
    if (warp >= NN) return;
    float v1 = h0f[(size_t)warp * 64 + lane];
    float v2 = h0f[(size_t)warp * 64 + lane + 32];
    float4 wsA = ((const float4*)g_was)[lane];
    float4 wsB = ((const float4*)g_was)[lane + 32];
    float4 wdA = ((const float4*)g_wad)[lane];
    float4 wdB = ((const float4*)g_wad)[lane + 32];
    float4 ps, pd;
    ps.x = v1 * wsA.x + v2 * wsB.x; ps.y = v1 * wsA.y + v2 * wsB.y;
    ps.z = v1 * wsA.z + v2 * wsB.z; ps.w = v1 * wsA.w + v2 * wsB.w;
    pd.x = v1 * wdA.x + v2 * wdB.x; pd.y = v1 * wdA.y + v2 * wdB.y;
    pd.z = v1 * wdA.z + v2 * wdB.z; pd.w = v1 * wdA.w + v2 * wdB.w;
#pragma unroll
    for (int o = 16; o; o >>= 1) {
        ps.x += __shfl_xor_sync(0xffffffffu, ps.x, o);
        ps.y += __shfl_xor_sync(0xffffffffu, ps.y, o);
        ps.z += __shfl_xor_sync(0xffffffffu, ps.z, o);
        ps.w += __shfl_xor_sync(0xffffffffu, ps.w, o);
        pd.x += __shfl_xor_sync(0xffffffffu, pd.x, o);
        pd.y += __shfl_xor_sync(0xffffffffu, pd.y, o);
        pd.z += __shfl_xor_sync(0xffffffffu, pd.z, o);
        pd.w += __shfl_xor_sync(0xffffffffu, pd.w, o);
    }
    if (lane == 0) {
        ((float4*)g_as)[warp] = ps;
        ((float4*)g_ad)[warp] = pd;
    }
}

// ---------------- alpha for layer 2: directly from h2 (C=16) --------------
__global__ void k_alpha2(const float* __restrict__ h2f, const float* __restrict__ as_,
                         const float* __restrict__ ad_) {
    int warp = (blockIdx.x * blockDim.x + threadIdx.x) >> 5;
    int lane = threadIdx.x & 31;
    if (warp >= NN) return;
    float v1 = h2f[(size_t)warp * 64 + lane];        // heads 0,1
    float v2 = h2f[(size_t)warp * 64 + lane + 32];   // heads 2,3
    float sA = v1 * as_[lane],      dA = v1 * ad_[lane];
    float sB = v2 * as_[32 + lane], dB = v2 * ad_[32 + lane];
#pragma unroll
    for (int o = 8; o; o >>= 1) {                    // segmented reduce (16)
        sA += __shfl_xor_sync(0xffffffffu, sA, o);
        sB += __shfl_xor_sync(0xffffffffu, sB, o);
        dA += __shfl_xor_sync(0xffffffffu, dA, o);
        dB += __shfl_xor_sync(0xffffffffu, dB, o);
    }
    if ((lane & 15) == 0) {
        int hb = lane >> 4;   // 0 or 1
        g_as[warp * 4 + hb]     = sA;
        g_as[warp * 4 + hb + 2] = sB;
        g_ad[warp * 4 + hb]     = dA;
        g_ad[warp * 4 + hb + 2] = dB;
    }
}

__device__ __forceinline__ float lrelu(float e) { return e > 0.f ? e : NEG * e; }

// ---------------- layer-1 aggregate IN h0 SPACE (64-wide), 4 heads --------
// One warp per node. Per edge: gather h0[src] (256 B) once, accumulate into
// 4 head-weighted accumulators. Output normalized [N][4][64]; bias + ELU
// deferred to the per-head GEMM that follows.
__global__ void k_agg1(const float* __restrict__ h0f, float* __restrict__ aggout) {
    __shared__ float4 sh_w[8][32];
    __shared__ int    sh_s[8][32];
    int warp = (blockIdx.x * blockDim.x + threadIdx.x) >> 5;
    int lane = threadIdx.x & 31;
    if (warp >= NN) return;
    int wip = threadIdx.x >> 5;
    int d = warp;
    int r0 = g_off[d], deg = g_off[d + 1] - r0;
    float4 adv = ((const float4*)g_ad)[d];

    float2 a0 = make_float2(0.f, 0.f), a1 = make_float2(0.f, 0.f);
    float2 a2 = make_float2(0.f, 0.f), a3 = make_float2(0.f, 0.f);
    float s0 = 0.f, s1 = 0.f, s2 = 0.f, s3 = 0.f;

    for (int base = 0; base < deg; base += 32) {
        int n = deg - base; if (n > 32) n = 32;
        float4 w = make_float4(0.f, 0.f, 0.f, 0.f); int s = 0;
        if (lane < n) {
            s = g_srcs[r0 + base + lane];
            float4 a = ((const float4*)g_as)[s];
            w.x = __expf(lrelu(a.x + adv.x));
            w.y = __expf(lrelu(a.y + adv.y));
            w.z = __expf(lrelu(a.z + adv.z));
            w.w = __expf(lrelu(a.w + adv.w));
        }
        s0 += w.x; s1 += w.y; s2 += w.z; s3 += w.w;
        sh_w[wip][lane] = w;
        sh_s[wip][lane] = s;
        __syncwarp();
#pragma unroll 4
        for (int j = 0; j < n; j++) {
            float4 wv = sh_w[wip][j];
            int sj = sh_s[wip][j];
            float2 v = ((const float2*)(h0f + (size_t)sj * 64))[lane];
            a0.x += v.x * wv.x; a0.y += v.y * wv.x;
            a1.x += v.x * wv.y; a1.y += v.y * wv.y;
            a2.x += v.x * wv.z; a2.y += v.y * wv.z;
            a3.x += v.x * wv.w; a3.y += v.y * wv.w;
        }
        __syncwarp();
    }
#pragma unroll
    for (int o = 16; o; o >>= 1) {
        s0 += __shfl_xor_sync(0xffffffffu, s0, o);
        s1 += __shfl_xor_sync(0xffffffffu, s1, o);
        s2 += __shfl_xor_sync(0xffffffffu, s2, o);
        s3 += __shfl_xor_sync(0xffffffffu, s3, o);
    }
    float i0 = 1.f / (s0 + EPSV), i1 = 1.f / (s1 + EPSV);
    float i2 = 1.f / (s2 + EPSV), i3 = 1.f / (s3 + EPSV);
    float* ob = aggout + (size_t)d * 256 + lane * 2;
    *(float2*)(ob)       = make_float2(a0.x * i0, a0.y * i0);
    *(float2*)(ob + 64)  = make_float2(a1.x * i1, a1.y * i1);
    *(float2*)(ob + 128) = make_float2(a2.x * i2, a2.y * i2);
    *(float2*)(ob + 192) = make_float2(a3.x * i3, a3.y * i3);
}

// ---------------- fused GAT layer-2 aggregate (C=16/head, no act) ---------
__global__ void k_agg2(const float* __restrict__ hfeat, const float* __restrict__ bias,
                       float* __restrict__ out) {
    __shared__ float4 sh_w[8][32];
    __shared__ int    sh_s[8][32];
    int warp = (blockIdx.x * blockDim.x + threadIdx.x) >> 5;
    int lane = threadIdx.x & 31;
    if (warp >= NN) return;
    int wip = threadIdx.x >> 5;
    int d = warp;
    int r0 = g_off[d], deg = g_off[d + 1] - r0;
    float4 adv = ((const float4*)g_ad)[d];
    int head = lane >> 3;

    float2 acc = make_float2(0.f, 0.f);
    float s0 = 0.f, s1 = 0.f, s2 = 0.f, s3 = 0.f;
    for (int base = 0; base < deg; base += 32) {
        int n = deg - base; if (n > 32) n = 32;
        float4 w = make_float4(0.f, 0.f, 0.f, 0.f); int s = 0;
        if (lane < n) {
            s = g_srcs[r0 + base + lane];
            float4 a = ((const float4*)g_as)[s];
            w.x = __expf(lrelu(a.x + adv.x));
            w.y = __expf(lrelu(a.y + adv.y));
            w.z = __expf(lrelu(a.z + adv.z));
            w.w = __expf(lrelu(a.w + adv.w));
        }
        s0 += w.x; s1 += w.y; s2 += w.z; s3 += w.w;
        sh_w[wip][lane] = w;
        sh_s[wip][lane] = s;
        __syncwarp();
#pragma unroll 4
        for (int j = 0; j < n; j++) {
            float4 wv = sh_w[wip][j];
            int sj = sh_s[wip][j];
            float wm = head == 0 ? wv.x : head == 1 ? wv.y : head == 2 ? wv.z : wv.w;
            float2 v = ((const float2*)(hfeat + (size_t)sj * 64))[lane];
            acc.x += v.x * wm;
            acc.y += v.y * wm;
        }
        __syncwarp();
    }
#pragma unroll
    for (int o = 16; o; o >>= 1) {
        s0 += __shfl_xor_sync(0xffffffffu, s0, o);
        s1 += __shfl_xor_sync(0xffffffffu, s1, o);
        s2 += __shfl_xor_sync(0xffffffffu, s2, o);
        s3 += __shfl_xor_sync(0xffffffffu, s3, o);
    }
    float im = head == 0 ? 1.f / (s0 + EPSV) : head == 1 ? 1.f / (s1 + EPSV)
             : head == 2 ? 1.f / (s2 + EPSV) : 1.f / (s3 + EPSV);
    float2 bv = ((const float2*)bias)[lane];
    float2 r;
    r.x = acc.x * im + bv.x;
    r.y = acc.y * im + bv.y;
    ((float2*)(out + (size_t)d * 64))[lane] = r;
}

// ---------------- decoder final layer [N,64] @ [64,4] ----------------
__global__ void k_dec2(const float* __restrict__ w2, const float* __restrict__ b2,
                       float* __restrict__ out) {
    int warp = (blockIdx.x * blockDim.x + threadIdx.x) >> 5;
    int lane = threadIdx.x & 31;
    if (warp >= NN) return;
    const float* mid = g_mid + (size_t)warp * 64;
    float4 acc = make_float4(0.f, 0.f, 0.f, 0.f);
#pragma unroll
    for (int k = lane; k < 64; k += 32) {
        float m = mid[k];
        float4 wv = ((const float4*)w2)[k];
        acc.x += m * wv.x; acc.y += m * wv.y;
        acc.z += m * wv.z; acc.w += m * wv.w;
    }
#pragma unroll
    for (int o = 16; o; o >>= 1) {
        acc.x += __shfl_xor_sync(0xffffffffu, acc.x, o);
        acc.y += __shfl_xor_sync(0xffffffffu, acc.y, o);
        acc.z += __shfl_xor_sync(0xffffffffu, acc.z, o);
        acc.w += __shfl_xor_sync(0xffffffffu, acc.w, o);
    }
    if (lane == 0) {
        out[warp * 4 + 0] = acc.x + b2[0];
        out[warp * 4 + 1] = acc.y + b2[1];
        out[warp * 4 + 2] = acc.z + b2[2];
        out[warp * 4 + 3] = acc.w + b2[3];
    }
}

// ---------------- launch ----------------
extern "C" void kernel_launch(void* const* d_in, const int* in_sizes, int n_in,
                              void* d_out, int out_size) {
    const float* x      = (const float*)d_in[0];
    const int*   ei     = (const int*)  d_in[1];
    const float* enc_w1 = (const float*)d_in[2];
    const float* enc_b1 = (const float*)d_in[3];
    const float* enc_w2 = (const float*)d_in[4];
    const float* enc_b2 = (const float*)d_in[5];
    const float* g1_w   = (const float*)d_in[6];
    const float* g1_as  = (const float*)d_in[7];
    const float* g1_ad  = (const float*)d_in[8];
    const float* g1_b   = (const float*)d_in[9];
    const float* g2_w   = (const float*)d_in[10];
    const float* g2_as  = (const float*)d_in[11];
    const float* g2_ad  = (const float*)d_in[12];
    const float* g2_b   = (const float*)d_in[13];
    const float* dec_w1 = (const float*)d_in[14];
    const float* dec_b1 = (const float*)d_in[15];
    const float* dec_w2 = (const float*)d_in[16];
    const float* dec_b2 = (const float*)d_in[17];
    float* out = (float*)d_out;

    float *mid, *h0, *agg, *o1, *h2, *o2;
    cudaGetSymbolAddress((void**)&mid, g_mid);
    cudaGetSymbolAddress((void**)&h0,  g_h0);
    cudaGetSymbolAddress((void**)&agg, g_agg);
    cudaGetSymbolAddress((void**)&o1,  g_o1);
    cudaGetSymbolAddress((void**)&h2,  g_h2);
    cudaGetSymbolAddress((void**)&o2,  g_o2);

    const int WPB = 6250;      // 50000 warps / 8 warps-per-block
    const int GY  = (NN + 127) / 128;

    // CSR build
    k_zero_deg<<<(NN + 255) / 256, 256>>>();
    k_count<<<(ETOT + 255) / 256, 256>>>(ei);
    k_bsum<<<NB1, 1024>>>();
    k_bscan<<<1, 64>>>();
    k_swrite<<<NB1, 1024>>>();
    k_scatter<<<(ETOT + 255) / 256, 256>>>(ei);

    // encoder
    k_enc1<<<(NN * 64 + 255) / 256, 256>>>(x, enc_w1, enc_b1);
    k_mma_gemm<0><<<dim3(1, GY), 256>>>(mid, enc_w2, enc_b2, h0, NN, 64, 64, 64, 64, 64, 0);

    // GAT layer 1: alpha from h0, aggregate in h0 space, per-head GEMM (+b, ELU)
    k_fold1<<<1, 256>>>(g1_w, g1_as, g1_ad);
    k_alpha1<<<WPB, 256>>>(h0);
    k_agg1<<<WPB, 256>>>(h0, agg);
    k_mma_gemm<2><<<dim3(1, GY, 4), 256>>>(agg, g1_w, g1_b, o1, NN, 64, 64, 256, 256, 256, 64);

    // GAT layer 2 (C=16, concat->64, no act)
    k_mma_gemm<0><<<dim3(1, GY), 256>>>(o1, g2_w, nullptr, h2, NN, 256, 64, 256, 64, 64, 0);
    k_alpha2<<<WPB, 256>>>(h2, g2_as, g2_ad);
    k_agg2<<<WPB, 256>>>(h2, g2_b, o2);

    // decoder
    k_mma_gemm<1><<<dim3(1, GY), 256>>>(o2, dec_w1, dec_b1, mid, NN, 64, 64, 64, 64, 64, 0);
    k_dec2<<<WPB, 256>>>(dec_w2, dec_b2, out);
}

// round 5
// speedup vs baseline: 1.9385x; 1.0881x over previous
#include <cuda_runtime.h>
#include <math.h>
#include <stdint.h>

#define NN 50000
#define NE 800000
#define ETOT (NE + NN)
#define NEG 0.2f
#define EPSV 1e-16f
#define NB1 49   // ceil(NN/1024)

// ---------------- scratch (device globals; no allocation allowed) ----------
__device__ __align__(16) float g_mid[NN * 64];
__device__ __align__(16) float g_h0 [NN * 64];
__device__ __align__(16) float g_agg[NN * 256];   // layer-1 aggregated h0 (per head)
__device__ __align__(16) float g_o1 [NN * 256];
__device__ __align__(16) float g_h2 [NN * 64];
__device__ __align__(16) float g_o2 [NN * 64];
__device__ __align__(16) float g_as [NN * 4];
__device__ __align__(16) float g_ad [NN * 4];
__device__ __align__(16) float g_was[256];
__device__ __align__(16) float g_wad[256];
__device__ int g_deg[NN];
__device__ int g_off[NN + 1];
__device__ int g_cur[NN];
__device__ int g_srcs[ETOT];
__device__ int g_bsum[NB1];

// ---------------- CSR build ----------------
__global__ void k_count(const int* __restrict__ ei) {
    int i = blockIdx.x * blockDim.x + threadIdx.x;
    if (i >= ETOT) return;
    int d = (i < NE) ? ei[NE + i] : (i - NE);
    atomicAdd(&g_deg[d], 1);
}

__global__ void k_bsum() {
    __shared__ int sh[1024];
    int t = threadIdx.x;
    int i = blockIdx.x * 1024 + t;
    sh[t] = (i < NN) ? g_deg[i] : 0;
    __syncthreads();
#pragma unroll
    for (int o = 512; o > 0; o >>= 1) {
        if (t < o) sh[t] += sh[t + o];
        __syncthreads();
    }
    if (t == 0) g_bsum[blockIdx.x] = sh[0];
}

// per-block exclusive scan; block base computed in-kernel from g_bsum
__global__ void k_swrite() {
    __shared__ int sh[1024];
    __shared__ int sb[64];
    __shared__ int sbase;
    int t = threadIdx.x;
    if (t < 64) sb[t] = (t < blockIdx.x && t < NB1) ? g_bsum[t] : 0;
    int i = blockIdx.x * 1024 + t;
    int v = (i < NN) ? g_deg[i] : 0;
    sh[t] = v;
    __syncthreads();
#pragma unroll
    for (int o = 1; o < 1024; o <<= 1) {
        int x = (t >= o) ? sh[t - o] : 0;
        __syncthreads();
        sh[t] += x;
        __syncthreads();
    }
    if (t == 0) {
        int b = 0;
#pragma unroll
        for (int j = 0; j < 64; j++) b += sb[j];
        sbase = b;
    }
    __syncthreads();
    int incl = sh[t];
    int base = sbase;
    if (i < NN) {
        int off = base + incl - v;
        g_off[i] = off;
        g_cur[i] = off;
        if (i == NN - 1) g_off[NN] = base + incl;
    }
}

__global__ void k_scatter(const int* __restrict__ ei) {
    int i = blockIdx.x * blockDim.x + threadIdx.x;
    if (i >= ETOT) return;
    int s, d;
    if (i < NE) { s = ei[i]; d = ei[NE + i]; }
    else        { s = i - NE; d = i - NE; }
    int p = atomicAdd(&g_cur[d], 1);
    g_srcs[p] = s;
}

// ---------------- encoder first layer (K=7) ----------------
__global__ void k_enc1(const float* __restrict__ x, const float* __restrict__ w1,
                       const float* __restrict__ b1) {
    int idx = blockIdx.x * blockDim.x + threadIdx.x;
    if (idx >= NN * 64) return;
    int n = idx >> 6, c = idx & 63;
    float s = b1[c];
#pragma unroll
    for (int k = 0; k < 7; k++) s += x[n * 7 + k] * w1[k * 64 + c];
    g_mid[idx] = fmaxf(s, 0.f);
}

// ---------------- tf32 tensor-core GEMM (3xTF32 split) ----------------
__device__ __forceinline__ float tf32_rn(float x) {
    uint32_t u;
    asm("cvt.rna.tf32.f32 %0, %1;" : "=r"(u) : "f"(x));
    return __uint_as_float(u);
}

__device__ __forceinline__ void mma_tf32(float4& d, const uint32_t a[4], const uint32_t b[2]) {
    asm volatile(
        "mma.sync.aligned.m16n8k8.row.col.f32.tf32.tf32.f32 "
        "{%0,%1,%2,%3},{%4,%5,%6,%7},{%8,%9},{%0,%1,%2,%3};\n"
        : "+f"(d.x), "+f"(d.y), "+f"(d.z), "+f"(d.w)
        : "r"(a[0]), "r"(a[1]), "r"(a[2]), "r"(a[3]), "r"(b[0]), "r"(b[1]));
}

template <int ACT>  // 0 none, 1 relu, 2 elu
__global__ void k_mma_gemm(const float* __restrict__ A, const float* __restrict__ B,
                           const float* __restrict__ bias, float* __restrict__ C,
                           int M, int K, int Nc, int lda, int ldb, int ldc, int zoff) {
    __shared__ float Ah[16][136], Al[16][136];
    __shared__ float Bh[16][72],  Bl[16][72];

    int zo = blockIdx.z * zoff;
    A += zo; B += zo; C += zo;
    if (bias) bias += zo;

    int tid  = threadIdx.x;
    int warp = tid >> 5, lane = tid & 31;
    int wm = warp >> 1, wn = warp & 1;
    int m0 = blockIdx.y * 128, n0 = blockIdx.x * 64;
    int grp = lane >> 2, tig = lane & 3;

    float4 acc[2][4];
#pragma unroll
    for (int i = 0; i < 2; i++)
#pragma unroll
        for (int j = 0; j < 4; j++) acc[i][j] = make_float4(0.f, 0.f, 0.f, 0.f);

    for (int k0 = 0; k0 < K; k0 += 16) {
#pragma unroll
        for (int r = 0; r < 2; r++) {
            int idx = tid + 256 * r;
            int m = idx >> 2, kq = idx & 3;
            int row = m0 + m;
            float4 v = make_float4(0.f, 0.f, 0.f, 0.f);
            if (row < M) v = *(const float4*)(A + (size_t)row * lda + k0 + 4 * kq);
            float h;
            h = tf32_rn(v.x); Ah[4*kq+0][m] = h; Al[4*kq+0][m] = tf32_rn(v.x - h);
            h = tf32_rn(v.y); Ah[4*kq+1][m] = h; Al[4*kq+1][m] = tf32_rn(v.y - h);
            h = tf32_rn(v.z); Ah[4*kq+2][m] = h; Al[4*kq+2][m] = tf32_rn(v.z - h);
            h = tf32_rn(v.w); Ah[4*kq+3][m] = h; Al[4*kq+3][m] = tf32_rn(v.w - h);
        }
        {
            int kk = tid >> 4, nq = tid & 15;
            float4 v = *(const float4*)(B + (size_t)(k0 + kk) * ldb + n0 + 4 * nq);
            float4 hv, lv;
            hv.x = tf32_rn(v.x); lv.x = tf32_rn(v.x - hv.x);
            hv.y = tf32_rn(v.y); lv.y = tf32_rn(v.y - hv.y);
            hv.z = tf32_rn(v.z); lv.z = tf32_rn(v.z - hv.z);
            hv.w = tf32_rn(v.w); lv.w = tf32_rn(v.w - hv.w);
            *(float4*)&Bh[kk][4 * nq] = hv;
            *(float4*)&Bl[kk][4 * nq] = lv;
        }
        __syncthreads();

#pragma unroll
        for (int ks = 0; ks < 2; ks++) {
            int kb = ks * 8;
            uint32_t aH[2][4], aL[2][4];
#pragma unroll
            for (int mt = 0; mt < 2; mt++) {
                int mb = wm * 32 + mt * 16 + grp;
                aH[mt][0] = __float_as_uint(Ah[kb + tig    ][mb]);
                aH[mt][1] = __float_as_uint(Ah[kb + tig    ][mb + 8]);
                aH[mt][2] = __float_as_uint(Ah[kb + tig + 4][mb]);
                aH[mt][3] = __float_as_uint(Ah[kb + tig + 4][mb + 8]);
                aL[mt][0] = __float_as_uint(Al[kb + tig    ][mb]);
                aL[mt][1] = __float_as_uint(Al[kb + tig    ][mb + 8]);
                aL[mt][2] = __float_as_uint(Al[kb + tig + 4][mb]);
                aL[mt][3] = __float_as_uint(Al[kb + tig + 4][mb + 8]);
            }
#pragma unroll
            for (int nt = 0; nt < 4; nt++) {
                int nb = wn * 32 + nt * 8 + grp;
                uint32_t bH[2], bL[2];
                bH[0] = __float_as_uint(Bh[kb + tig    ][nb]);
                bH[1] = __float_as_uint(Bh[kb + tig + 4][nb]);
                bL[0] = __float_as_uint(Bl[kb + tig    ][nb]);
                bL[1] = __float_as_uint(Bl[kb + tig + 4][nb]);
#pragma unroll
                for (int mt = 0; mt < 2; mt++) {
                    mma_tf32(acc[mt][nt], aH[mt], bH);
                    mma_tf32(acc[mt][nt], aL[mt], bH);
                    mma_tf32(acc[mt][nt], aH[mt], bL);
                }
            }
        }
        __syncthreads();
    }

#pragma unroll
    for (int mt = 0; mt < 2; mt++) {
#pragma unroll
        for (int nt = 0; nt < 4; nt++) {
            int col = n0 + wn * 32 + nt * 8 + 2 * tig;
            float b0 = bias ? bias[col] : 0.f;
            float b1 = bias ? bias[col + 1] : 0.f;
            int rt_ = m0 + wm * 32 + mt * 16 + grp;
            float2 v0 = make_float2(acc[mt][nt].x + b0, acc[mt][nt].y + b1);
            float2 v1 = make_float2(acc[mt][nt].z + b0, acc[mt][nt].w + b1);
            if (ACT == 1) {
                v0.x = fmaxf(v0.x, 0.f); v0.y = fmaxf(v0.y, 0.f);
                v1.x = fmaxf(v1.x, 0.f); v1.y = fmaxf(v1.y, 0.f);
            } else if (ACT == 2) {
                v0.x = v0.x > 0.f ? v0.x : expm1f(v0.x);
                v0.y = v0.y > 0.f ? v0.y : expm1f(v0.y);
                v1.x = v1.x > 0.f ? v1.x : expm1f(v1.x);
                v1.y = v1.y > 0.f ? v1.y : expm1f(v1.y);
            }
            if (rt_ < M)     *(float2*)(C + (size_t)rt_ * ldc + col)       = v0;
            if (rt_ + 8 < M) *(float2*)(C + (size_t)(rt_ + 8) * ldc + col) = v1;
        }
    }
}

// ---------------- fold g1_w with attention vectors: waS/waD [64][4] -------
__global__ void k_fold1(const float* __restrict__ w, const float* __restrict__ as_,
                        const float* __restrict__ ad_) {
    int t = threadIdx.x;          // 256 threads: t = k*4 + h
    int k = t >> 2, h = t & 3;
    float s = 0.f, d = 0.f;
#pragma unroll
    for (int c = 0; c < 64; c++) {
        float v = w[k * 256 + h * 64 + c];
        s += v * as_[h * 64 + c];
        d += v * ad_[h * 64 + c];
    }
    g_was[t] = s;
    g_wad[t] = d;
}

// ---------------- alpha for layer 1: from h0 via folded weights -----------
__global__ void k_alpha1(const float* __restrict__ h0f) {
    int warp = (blockIdx.x * blockDim.x + threadIdx.x) >> 5;
    int lane = threadIdx.x & 31;
    if (warp >= NN) return;
    float v1 = h0f[(size_t)warp * 64 + lane];
    float v2 = h0f[(size_t)warp * 64 + lane + 32];
    float4 wsA = ((const float4*)g_was)[lane];
    float4 wsB = ((const float4*)g_was)[lane + 32];
    float4 wdA = ((const float4*)g_wad)[lane];
    float4 wdB = ((const float4*)g_wad)[lane + 32];
    float4 ps, pd;
    ps.x = v1 * wsA.x + v2 * wsB.x; ps.y = v1 * wsA.y + v2 * wsB.y;
    ps.z = v1 * wsA.z + v2 * wsB.z; ps.w = v1 * wsA.w + v2 * wsB.w;
    pd.x = v1 * wdA.x + v2 * wdB.x; pd.y = v1 * wdA.y + v2 * wdB.y;
    pd.z = v1 * wdA.z + v2 * wdB.z; pd.w = v1 * wdA.w + v2 * wdB.w;
#pragma unroll
    for (int o = 16; o; o >>= 1) {
        ps.x += __shfl_xor_sync(0xffffffffu, ps.x, o);
        ps.y += __shfl_xor_sync(0xffffffffu, ps.y, o);
        ps.z += __shfl_xor_sync(0xffffffffu, ps.z, o);
        ps.w += __shfl_xor_sync(0xffffffffu, ps.w, o);
        pd.x += __shfl_xor_sync(0xffffffffu, pd.x, o);
        pd.y += __shfl_xor_sync(0xffffffffu, pd.y, o);
        pd.z += __shfl_xor_sync(0xffffffffu, pd.z, o);
        pd.w += __shfl_xor_sync(0xffffffffu, pd.w, o);
    }
    if (lane == 0) {
        ((float4*)g_as)[warp] = ps;
        ((float4*)g_ad)[warp] = pd;
    }
}

// ---------------- alpha for layer 2: directly from h2 (C=16) --------------
__global__ void k_alpha2(const float* __restrict__ h2f, const float* __restrict__ as_,
                         const float* __restrict__ ad_) {
    int warp = (blockIdx.x * blockDim.x + threadIdx.x) >> 5;
    int lane = threadIdx.x & 31;
    if (warp >= NN) return;
    float v1 = h2f[(size_t)warp * 64 + lane];        // heads 0,1
    float v2 = h2f[(size_t)warp * 64 + lane + 32];   // heads 2,3
    float sA = v1 * as_[lane],      dA = v1 * ad_[lane];
    float sB = v2 * as_[32 + lane], dB = v2 * ad_[32 + lane];
#pragma unroll
    for (int o = 8; o; o >>= 1) {                    // segmented reduce (16)
        sA += __shfl_xor_sync(0xffffffffu, sA, o);
        sB += __shfl_xor_sync(0xffffffffu, sB, o);
        dA += __shfl_xor_sync(0xffffffffu, dA, o);
        dB += __shfl_xor_sync(0xffffffffu, dB, o);
    }
    if ((lane & 15) == 0) {
        int hb = lane >> 4;   // 0 or 1
        g_as[warp * 4 + hb]     = sA;
        g_as[warp * 4 + hb + 2] = sB;
        g_ad[warp * 4 + hb]     = dA;
        g_ad[warp * 4 + hb + 2] = dB;
    }
}

__device__ __forceinline__ float lrelu(float e) { return e > 0.f ? e : NEG * e; }

// ---------------- layer-1 aggregate IN h0 SPACE (64-wide), 4 heads --------
__global__ void k_agg1(const float* __restrict__ h0f, float* __restrict__ aggout) {
    __shared__ float4 sh_w[8][32];
    __shared__ int    sh_s[8][32];
    int warp = (blockIdx.x * blockDim.x + threadIdx.x) >> 5;
    int lane = threadIdx.x & 31;
    if (warp >= NN) return;
    int wip = threadIdx.x >> 5;
    int d = warp;
    int r0 = g_off[d], deg = g_off[d + 1] - r0;
    float4 adv = ((const float4*)g_ad)[d];

    float2 a0 = make_float2(0.f, 0.f), a1 = make_float2(0.f, 0.f);
    float2 a2 = make_float2(0.f, 0.f), a3 = make_float2(0.f, 0.f);
    float s0 = 0.f, s1 = 0.f, s2 = 0.f, s3 = 0.f;

    for (int base = 0; base < deg; base += 32) {
        int n = deg - base; if (n > 32) n = 32;
        float4 w = make_float4(0.f, 0.f, 0.f, 0.f); int s = 0;
        if (lane < n) {
            s = g_srcs[r0 + base + lane];
            float4 a = ((const float4*)g_as)[s];
            w.x = __expf(lrelu(a.x + adv.x));
            w.y = __expf(lrelu(a.y + adv.y));
            w.z = __expf(lrelu(a.z + adv.z));
            w.w = __expf(lrelu(a.w + adv.w));
        }
        s0 += w.x; s1 += w.y; s2 += w.z; s3 += w.w;
        sh_w[wip][lane] = w;
        sh_s[wip][lane] = s;
        __syncwarp();
#pragma unroll 4
        for (int j = 0; j < n; j++) {
            float4 wv = sh_w[wip][j];
            int sj = sh_s[wip][j];
            float2 v = ((const float2*)(h0f + (size_t)sj * 64))[lane];
            a0.x += v.x * wv.x; a0.y += v.y * wv.x;
            a1.x += v.x * wv.y; a1.y += v.y * wv.y;
            a2.x += v.x * wv.z; a2.y += v.y * wv.z;
            a3.x += v.x * wv.w; a3.y += v.y * wv.w;
        }
        __syncwarp();
    }
#pragma unroll
    for (int o = 16; o; o >>= 1) {
        s0 += __shfl_xor_sync(0xffffffffu, s0, o);
        s1 += __shfl_xor_sync(0xffffffffu, s1, o);
        s2 += __shfl_xor_sync(0xffffffffu, s2, o);
        s3 += __shfl_xor_sync(0xffffffffu, s3, o);
    }
    float i0 = 1.f / (s0 + EPSV), i1 = 1.f / (s1 + EPSV);
    float i2 = 1.f / (s2 + EPSV), i3 = 1.f / (s3 + EPSV);
    float* ob = aggout + (size_t)d * 256 + lane * 2;
    *(float2*)(ob)       = make_float2(a0.x * i0, a0.y * i0);
    *(float2*)(ob + 64)  = make_float2(a1.x * i1, a1.y * i1);
    *(float2*)(ob + 128) = make_float2(a2.x * i2, a2.y * i2);
    *(float2*)(ob + 192) = make_float2(a3.x * i3, a3.y * i3);
}

// ---------------- fused GAT layer-2 aggregate (C=16/head, no act) ---------
__global__ void k_agg2(const float* __restrict__ hfeat, const float* __restrict__ bias,
                       float* __restrict__ out) {
    __shared__ float4 sh_w[8][32];
    __shared__ int    sh_s[8][32];
    int warp = (blockIdx.x * blockDim.x + threadIdx.x) >> 5;
    int lane = threadIdx.x & 31;
    if (warp >= NN) return;
    int wip = threadIdx.x >> 5;
    int d = warp;
    int r0 = g_off[d], deg = g_off[d + 1] - r0;
    float4 adv = ((const float4*)g_ad)[d];
    int head = lane >> 3;

    float2 acc = make_float2(0.f, 0.f);
    float s0 = 0.f, s1 = 0.f, s2 = 0.f, s3 = 0.f;
    for (int base = 0; base < deg; base += 32) {
        int n = deg - base; if (n > 32) n = 32;
        float4 w = make_float4(0.f, 0.f, 0.f, 0.f); int s = 0;
        if (lane < n) {
            s = g_srcs[r0 + base + lane];
            float4 a = ((const float4*)g_as)[s];
            w.x = __expf(lrelu(a.x + adv.x));
            w.y = __expf(lrelu(a.y + adv.y));
            w.z = __expf(lrelu(a.z + adv.z));
            w.w = __expf(lrelu(a.w + adv.w));
        }
        s0 += w.x; s1 += w.y; s2 += w.z; s3 += w.w;
        sh_w[wip][lane] = w;
        sh_s[wip][lane] = s;
        __syncwarp();
#pragma unroll 4
        for (int j = 0; j < n; j++) {
            float4 wv = sh_w[wip][j];
            int sj = sh_s[wip][j];
            float wm = head == 0 ? wv.x : head == 1 ? wv.y : head == 2 ? wv.z : wv.w;
            float2 v = ((const float2*)(hfeat + (size_t)sj * 64))[lane];
            acc.x += v.x * wm;
            acc.y += v.y * wm;
        }
        __syncwarp();
    }
#pragma unroll
    for (int o = 16; o; o >>= 1) {
        s0 += __shfl_xor_sync(0xffffffffu, s0, o);
        s1 += __shfl_xor_sync(0xffffffffu, s1, o);
        s2 += __shfl_xor_sync(0xffffffffu, s2, o);
        s3 += __shfl_xor_sync(0xffffffffu, s3, o);
    }
    float im = head == 0 ? 1.f / (s0 + EPSV) : head == 1 ? 1.f / (s1 + EPSV)
             : head == 2 ? 1.f / (s2 + EPSV) : 1.f / (s3 + EPSV);
    float2 bv = ((const float2*)bias)[lane];
    float2 r;
    r.x = acc.x * im + bv.x;
    r.y = acc.y * im + bv.y;
    ((float2*)(out + (size_t)d * 64))[lane] = r;
}

// ---------------- decoder final layer [N,64] @ [64,4] ----------------
__global__ void k_dec2(const float* __restrict__ w2, const float* __restrict__ b2,
                       float* __restrict__ out) {
    int warp = (blockIdx.x * blockDim.x + threadIdx.x) >> 5;
    int lane = threadIdx.x & 31;
    if (warp >= NN) return;
    const float* mid = g_mid + (size_t)warp * 64;
    float4 acc = make_float4(0.f, 0.f, 0.f, 0.f);
#pragma unroll
    for (int k = lane; k < 64; k += 32) {
        float m = mid[k];
        float4 wv = ((const float4*)w2)[k];
        acc.x += m * wv.x; acc.y += m * wv.y;
        acc.z += m * wv.z; acc.w += m * wv.w;
    }
#pragma unroll
    for (int o = 16; o; o >>= 1) {
        acc.x += __shfl_xor_sync(0xffffffffu, acc.x, o);
        acc.y += __shfl_xor_sync(0xffffffffu, acc.y, o);
        acc.z += __shfl_xor_sync(0xffffffffu, acc.z, o);
        acc.w += __shfl_xor_sync(0xffffffffu, acc.w, o);
    }
    if (lane == 0) {
        out[warp * 4 + 0] = acc.x + b2[0];
        out[warp * 4 + 1] = acc.y + b2[1];
        out[warp * 4 + 2] = acc.z + b2[2];
        out[warp * 4 + 3] = acc.w + b2[3];
    }
}

// ---------------- launch ----------------
extern "C" void kernel_launch(void* const* d_in, const int* in_sizes, int n_in,
                              void* d_out, int out_size) {
    const float* x      = (const float*)d_in[0];
    const int*   ei     = (const int*)  d_in[1];
    const float* enc_w1 = (const float*)d_in[2];
    const float* enc_b1 = (const float*)d_in[3];
    const float* enc_w2 = (const float*)d_in[4];
    const float* enc_b2 = (const float*)d_in[5];
    const float* g1_w   = (const float*)d_in[6];
    const float* g1_as  = (const float*)d_in[7];
    const float* g1_ad  = (const float*)d_in[8];
    const float* g1_b   = (const float*)d_in[9];
    const float* g2_w   = (const float*)d_in[10];
    const float* g2_as  = (const float*)d_in[11];
    const float* g2_ad  = (const float*)d_in[12];
    const float* g2_b   = (const float*)d_in[13];
    const float* dec_w1 = (const float*)d_in[14];
    const float* dec_b1 = (const float*)d_in[15];
    const float* dec_w2 = (const float*)d_in[16];
    const float* dec_b2 = (const float*)d_in[17];
    float* out = (float*)d_out;

    float *mid, *h0, *agg, *o1, *h2, *o2;
    cudaGetSymbolAddress((void**)&mid, g_mid);
    cudaGetSymbolAddress((void**)&h0,  g_h0);
    cudaGetSymbolAddress((void**)&agg, g_agg);
    cudaGetSymbolAddress((void**)&o1,  g_o1);
    cudaGetSymbolAddress((void**)&h2,  g_h2);
    cudaGetSymbolAddress((void**)&o2,  g_o2);
    void* degp;
    cudaGetSymbolAddress(&degp, g_deg);

    // one-time stream/event setup (host objects only; no device allocation)
    static cudaStream_t s1 = 0, s2 = 0;
    static cudaEvent_t evRoot = 0, evCSR = 0, evFold = 0;
    static int inited = 0;
    if (!inited) {
        cudaStreamCreateWithFlags(&s1, cudaStreamNonBlocking);
        cudaStreamCreateWithFlags(&s2, cudaStreamNonBlocking);
        cudaEventCreateWithFlags(&evRoot, cudaEventDisableTiming);
        cudaEventCreateWithFlags(&evCSR,  cudaEventDisableTiming);
        cudaEventCreateWithFlags(&evFold, cudaEventDisableTiming);
        inited = 1;
    }

    const int WPB = 6250;      // 50000 warps / 8 warps-per-block
    const int GY  = (NN + 127) / 128;

    // ---- fork ----
    cudaEventRecord(evRoot, 0);
    cudaStreamWaitEvent(s1, evRoot, 0);
    cudaStreamWaitEvent(s2, evRoot, 0);

    // branch s1: CSR build
    cudaMemsetAsync(degp, 0, NN * sizeof(int), s1);
    k_count<<<(ETOT + 255) / 256, 256, 0, s1>>>(ei);
    k_bsum<<<NB1, 1024, 0, s1>>>();
    k_swrite<<<NB1, 1024, 0, s1>>>();
    k_scatter<<<(ETOT + 255) / 256, 256, 0, s1>>>(ei);
    cudaEventRecord(evCSR, s1);

    // branch s2: fold attention weights
    k_fold1<<<1, 256, 0, s2>>>(g1_w, g1_as, g1_ad);
    cudaEventRecord(evFold, s2);

    // main: encoder chain
    k_enc1<<<(NN * 64 + 255) / 256, 256>>>(x, enc_w1, enc_b1);
    k_mma_gemm<0><<<dim3(1, GY), 256>>>(mid, enc_w2, enc_b2, h0, NN, 64, 64, 64, 64, 64, 0);
    cudaStreamWaitEvent(0, evFold, 0);
    k_alpha1<<<WPB, 256>>>(h0);

    // ---- join: aggregation needs CSR + alpha ----
    cudaStreamWaitEvent(0, evCSR, 0);
    k_agg1<<<WPB, 256>>>(h0, agg);
    k_mma_gemm<2><<<dim3(1, GY, 4), 256>>>(agg, g1_w, g1_b, o1, NN, 64, 64, 256, 256, 256, 64);

    // GAT layer 2 (C=16, concat->64, no act)
    k_mma_gemm<0><<<dim3(1, GY), 256>>>(o1, g2_w, nullptr, h2, NN, 256, 64, 256, 64, 64, 0);
    k_alpha2<<<WPB, 256>>>(h2, g2_as, g2_ad);
    k_agg2<<<WPB, 256>>>(h2, g2_b, o2);

    // decoder
    k_mma_gemm<1><<<dim3(1, GY), 256>>>(o2, dec_w1, dec_b1, mid, NN, 64, 64, 64, 64, 64, 0);
    k_dec2<<<WPB, 256>>>(dec_w2, dec_b2, out);
}